// round 13
// baseline (speedup 1.0000x reference)
#include <cuda_runtime.h>
#include <cuda_bf16.h>
#include <cstdint>

#define NN 100000
#define EE 600000
#define HH 128
#define ZZ 64
#define BIN 198
#define SCAN_BLOCKS ((NN + 1023) / 1024)   // 98
#define MTILES ((NN + 127) / 128)          // 782

// ---------------- device scratch (no allocations allowed) ----------------
__device__ int   g_i64;
__device__ int   g_counts[NN];
__device__ int   g_off[NN + 1];
__device__ int   g_cursor[NN];
__device__ int   g_csr[EE];
__device__ int   g_bsums[SCAN_BLOCKS];
__device__ int   g_bsum_ex[SCAN_BLOCKS];
__device__ float g_ts[(size_t)NN * 128];               // GEMM out, s-half (streamed)
__device__ float g_tn[(size_t)NN * 128];               // GEMM out, n-half (gathered; L2-hot)
__device__ float g_q[(size_t)NN * 6];                  // head per-node outputs
__device__ __nv_bfloat16 g_Ahi[(size_t)4 * NN * 256];  // per-layer concat A, hi part
__device__ __nv_bfloat16 g_Alo[(size_t)4 * NN * 256];  // lo part
__device__ __nv_bfloat16 g_Whi[4 * 256 * 256];         // [layer][n(256)][k(256)]
__device__ __nv_bfloat16 g_Wlo[4 * 256 * 256];
__device__ float g_Wf[4 * 256 * 256];                  // fp32 [l][k][n] (fallback path)

// ---------------- arch feature gate ----------------
#if defined(__CUDA_ARCH_FEAT_SM103_ALL) || defined(__CUDA_ARCH_FEAT_SM100_ALL) || \
    defined(__CUDA_ARCH_FEAT_SM101_ALL) || defined(__CUDA_ARCH_FEAT_SM110_ALL)
#define TC_OK 1
#else
#define TC_OK 0
#endif

// ---------------- L2 policy-based cache hints ----------------
__device__ __forceinline__ uint64_t pol_evict_last() {
    uint64_t p;
    asm("createpolicy.fractional.L2::evict_last.b64 %0, 1.0;" : "=l"(p));
    return p;
}
__device__ __forceinline__ uint64_t pol_evict_first() {
    uint64_t p;
    asm("createpolicy.fractional.L2::evict_first.b64 %0, 1.0;" : "=l"(p));
    return p;
}
__device__ __forceinline__ float4 ldg_hint_f4(const float4* p, uint64_t pol) {
    float4 v;
    asm volatile("ld.global.nc.L2::cache_hint.v4.f32 {%0,%1,%2,%3}, [%4], %5;"
                 : "=f"(v.x), "=f"(v.y), "=f"(v.z), "=f"(v.w) : "l"(p), "l"(pol));
    return v;
}
__device__ __forceinline__ uint4 ldg_hint_u4(const void* p, uint64_t pol) {
    uint4 v;
    asm volatile("ld.global.nc.L2::cache_hint.v4.b32 {%0,%1,%2,%3}, [%4], %5;"
                 : "=r"(v.x), "=r"(v.y), "=r"(v.z), "=r"(v.w) : "l"(p), "l"(pol));
    return v;
}
__device__ __forceinline__ void stg_hint_u4(void* p, uint4 v, uint64_t pol) {
    asm volatile("st.global.L2::cache_hint.v4.b32 [%0], {%1,%2,%3,%4}, %5;"
                 :: "l"(p), "r"(v.x), "r"(v.y), "r"(v.z), "r"(v.w), "l"(pol) : "memory");
}
__device__ __forceinline__ void stg_hint_f(float* p, float v, uint64_t pol) {
    asm volatile("st.global.L2::cache_hint.f32 [%0], %1, %2;"
                 :: "l"(p), "f"(v), "l"(pol) : "memory");
}

// ---------------- PTX helpers ----------------
__device__ __forceinline__ uint32_t elect_one_pred() {
    uint32_t pred;
    asm volatile("{\n\t.reg .pred p;\n\telect.sync _|p, 0xFFFFFFFF;\n\tselp.b32 %0, 1, 0, p;\n\t}"
                 : "=r"(pred));
    return pred;
}
__device__ __forceinline__ uint32_t smem_to_u32(const void* p) {
    uint32_t a;
    asm("{ .reg .u64 t; cvta.to.shared.u64 t, %1; cvt.u32.u64 %0, t; }" : "=r"(a) : "l"(p));
    return a;
}
#define SMEM_SWIZZLE_128B(x) ((x) ^ (((x) >> 3) & 0x70))

#define TCGEN05_ALLOC(sa, n) \
    asm volatile("tcgen05.alloc.cta_group::1.sync.aligned.shared::cta.b32 [%0], %1;" \
                 :: "r"((uint32_t)(sa)), "r"((uint32_t)(n)) : "memory")
#define TCGEN05_DEALLOC(t, n) \
    asm volatile("tcgen05.dealloc.cta_group::1.sync.aligned.b32 %0, %1;" :: "r"(t), "r"(n))
#define TCGEN05_RELINQ() \
    asm volatile("tcgen05.relinquish_alloc_permit.cta_group::1.sync.aligned;")
#define TCGEN05_COMMIT(mb) \
    asm volatile("tcgen05.commit.cta_group::1.mbarrier::arrive::one.shared::cluster.b64 [%0];" \
                 :: "r"((uint32_t)(mb)) : "memory")
#define TCGEN05_FENCE_AFTER() asm volatile("tcgen05.fence::after_thread_sync;" ::: "memory")
#define TCGEN05_FENCE_BEFORE() asm volatile("tcgen05.fence::before_thread_sync;" ::: "memory")
#define TCGEN05_WAIT_LD() asm volatile("tcgen05.wait::ld.sync.aligned;" ::: "memory")
#define FENCE_ASYNC() asm volatile("fence.proxy.async.shared::cta;" ::: "memory")
#define MBARRIER_INIT(mb, c) \
    asm volatile("mbarrier.init.shared.b64 [%0], %1;" :: "r"((uint32_t)(mb)), "r"((uint32_t)(c)) : "memory")

#define MBARRIER_WAIT_PARITY(mb, ph) do { \
    uint32_t _m = (uint32_t)(mb), _p = (uint32_t)(ph), _d; \
    asm volatile("{\n\t.reg .pred p;\n\t" \
        "mbarrier.try_wait.parity.acquire.cta.shared::cta.b64 p, [%1], %2;\n\t" \
        "selp.b32 %0, 1, 0, p;\n\t}" : "=r"(_d) : "r"(_m), "r"(_p) : "memory"); \
    if (!_d) { \
        asm volatile("{\n\t.reg .pred P1;\n\t" \
            "WL_%=:\n\t" \
            "mbarrier.try_wait.parity.acquire.cta.shared::cta.b64 P1, [%0], %1, 0x989680;\n\t" \
            "@P1 bra.uni WD_%=;\n\tbra.uni WL_%=;\n\tWD_%=:\n\t}" \
            :: "r"(_m), "r"(_p) : "memory"); \
    } \
} while (0)

#define TCGEN05_LD_X32(r, ta) \
    asm volatile("tcgen05.ld.sync.aligned.32x32b.x32.b32 " \
        "{%0, %1, %2, %3, %4, %5, %6, %7, %8, %9, %10, %11, %12, %13, %14, %15, " \
        "%16, %17, %18, %19, %20, %21, %22, %23, %24, %25, %26, %27, %28, %29, %30, %31}, [%32];" \
        : "=r"((r)[0]), "=r"((r)[1]), "=r"((r)[2]), "=r"((r)[3]), "=r"((r)[4]), "=r"((r)[5]), \
          "=r"((r)[6]), "=r"((r)[7]), "=r"((r)[8]), "=r"((r)[9]), "=r"((r)[10]), "=r"((r)[11]), \
          "=r"((r)[12]), "=r"((r)[13]), "=r"((r)[14]), "=r"((r)[15]), "=r"((r)[16]), "=r"((r)[17]), \
          "=r"((r)[18]), "=r"((r)[19]), "=r"((r)[20]), "=r"((r)[21]), "=r"((r)[22]), "=r"((r)[23]), \
          "=r"((r)[24]), "=r"((r)[25]), "=r"((r)[26]), "=r"((r)[27]), "=r"((r)[28]), "=r"((r)[29]), \
          "=r"((r)[30]), "=r"((r)[31]) : "r"(ta))

#if TC_OK
__device__ __forceinline__ void mma_bf16_ss(uint32_t d, uint64_t a, uint64_t b,
                                            uint32_t idesc, bool en) {
    uint32_t e = en ? 1u : 0u;
    asm volatile(
        "{\n\t.reg .pred p;\n\tsetp.ne.u32 p, %5, 0;\n\t"
        "tcgen05.mma.cta_group::1.kind::f16 [%0], %1, %2, %3, {%4, %4, %4, %4}, p;\n\t}"
        :: "r"(d), "l"(a), "l"(b), "r"(idesc), "r"(0u), "r"(e) : "memory");
}
#endif

__device__ __forceinline__ uint64_t make_desc(uint32_t addr) {
    const uint64_t base = (2ull << 61) | (1ull << 46) | (64ull << 32) | (1ull << 16);
    return base | ((uint64_t)(addr >> 4) & 0x3FFF);
}

#define MMA_IDESC ((1u << 4) | (1u << 7) | (1u << 10) | ((128u / 8) << 17) | ((128u / 16) << 24))

__device__ __forceinline__ int2 edge_pair(const void* edges, int e) {
    if (g_i64) {
        longlong2 v = ((const longlong2*)edges)[e];
        return make_int2((int)v.x, (int)v.y);
    }
    return ((const int2*)edges)[e];
}
__device__ __forceinline__ void bf16_split(float x, __nv_bfloat16& h, __nv_bfloat16& l) {
    h = __float2bfloat16(x);
    l = __float2bfloat16(x - __bfloat162float(h));
}
__device__ __forceinline__ unsigned long long pack2(float x, float y) {
    unsigned long long d;
    asm("mov.b64 %0, {%1, %2};" : "=l"(d) : "f"(x), "f"(y));
    return d;
}
__device__ __forceinline__ unsigned long long fma2(unsigned long long a,
                                                   unsigned long long b,
                                                   unsigned long long c) {
    unsigned long long d;
    asm("fma.rn.f32x2 %0, %1, %2, %3;" : "=l"(d) : "l"(a), "l"(b), "l"(c));
    return d;
}

// ---------------- gather: MLP=4 + index prefetch + 2-wide remainder tier ---------
__device__ __forceinline__ float4 gather_agg(const float* __restrict__ tn,
                                             int s0, int s1, int lane, uint64_t pel) {
    float4 acc = make_float4(0.f, 0.f, 0.f, 0.f);
    int e = s0;
    if (e + 4 <= s1) {
        int i0 = g_csr[e], i1 = g_csr[e + 1], i2 = g_csr[e + 2], i3 = g_csr[e + 3];
        while (true) {
            int ne = e + 4;
            float4 v0 = ldg_hint_f4((const float4*)(tn + (size_t)i0 * 128) + lane, pel);
            float4 v1 = ldg_hint_f4((const float4*)(tn + (size_t)i1 * 128) + lane, pel);
            float4 v2 = ldg_hint_f4((const float4*)(tn + (size_t)i2 * 128) + lane, pel);
            float4 v3 = ldg_hint_f4((const float4*)(tn + (size_t)i3 * 128) + lane, pel);
            bool more = (ne + 4 <= s1);
            if (more) {                     // prefetch next batch's indices NOW
                i0 = g_csr[ne]; i1 = g_csr[ne + 1];
                i2 = g_csr[ne + 2]; i3 = g_csr[ne + 3];
            }
            acc.x += (v0.x + v1.x) + (v2.x + v3.x);
            acc.y += (v0.y + v1.y) + (v2.y + v3.y);
            acc.z += (v0.z + v1.z) + (v2.z + v3.z);
            acc.w += (v0.w + v1.w) + (v2.w + v3.w);
            e = ne;
            if (!more) break;
        }
    }
    if (e + 2 <= s1) {                      // 2-wide tier
        int i0 = g_csr[e], i1 = g_csr[e + 1];
        float4 v0 = ldg_hint_f4((const float4*)(tn + (size_t)i0 * 128) + lane, pel);
        float4 v1 = ldg_hint_f4((const float4*)(tn + (size_t)i1 * 128) + lane, pel);
        acc.x += v0.x + v1.x;
        acc.y += v0.y + v1.y;
        acc.z += v0.z + v1.z;
        acc.w += v0.w + v1.w;
        e += 2;
    }
    if (e < s1) {
        int s = g_csr[e];
        float4 v = ldg_hint_f4((const float4*)(tn + (size_t)s * 128) + lane, pel);
        acc.x += v.x; acc.y += v.y; acc.z += v.z; acc.w += v.w;
    }
    return acc;
}

// ---------------- CSR construction ----------------
__global__ void zero_counts_kernel(const void* edges) {
    int i = blockIdx.x * blockDim.x + threadIdx.x;
    if (i < NN) g_counts[i] = 0;
    if (blockIdx.x == 0 && threadIdx.x < 32) {
        const long long* p = (const long long*)edges;
        long long v = p[threadIdx.x];
        bool ok = (v >= 0 && v < NN);
        unsigned m = __ballot_sync(0xffffffff, ok);
        if (threadIdx.x == 0) g_i64 = (m == 0xffffffffu) ? 1 : 0;
    }
}
__global__ void count_kernel(const void* edges) {
    int e = blockIdx.x * blockDim.x + threadIdx.x;
    if (e < EE) atomicAdd(&g_counts[edge_pair(edges, e).y], 1);
}
__global__ void scan_block_kernel() {
    __shared__ int s[1024];
    int t = threadIdx.x;
    int i = blockIdx.x * 1024 + t;
    int v = (i < NN) ? g_counts[i] : 0;
    s[t] = v;
    __syncthreads();
#pragma unroll
    for (int d = 1; d < 1024; d <<= 1) {
        int x = (t >= d) ? s[t - d] : 0;
        __syncthreads();
        s[t] += x;
        __syncthreads();
    }
    if (i < NN) g_off[i] = s[t] - v;
    if (t == 1023) g_bsums[blockIdx.x] = s[1023];
}
__global__ void scan_tops_kernel() {
    __shared__ int s[128];
    int t = threadIdx.x;
    int v = (t < SCAN_BLOCKS) ? g_bsums[t] : 0;
    s[t] = v;
    __syncthreads();
#pragma unroll
    for (int d = 1; d < 128; d <<= 1) {
        int x = (t >= d) ? s[t - d] : 0;
        __syncthreads();
        s[t] += x;
        __syncthreads();
    }
    if (t < SCAN_BLOCKS) g_bsum_ex[t] = s[t] - v;
}
__global__ void scan_add_kernel() {
    int i = blockIdx.x * 1024 + threadIdx.x;
    if (i < NN) {
        int o = g_off[i] + g_bsum_ex[blockIdx.x];
        g_off[i] = o;
        g_cursor[i] = o;
    }
    if (i == 0) g_off[NN] = EE;
}
__global__ void scatter_kernel(const void* edges) {
    int e = blockIdx.x * blockDim.x + threadIdx.x;
    if (e < EE) {
        int2 p = edge_pair(edges, e);
        g_csr[atomicAdd(&g_cursor[p.y], 1)] = p.x;
    }
}

// ---------------- weight transpose+split ----------------
__global__ void wconv_kernel(const float* __restrict__ Wbs, const float* __restrict__ Wbn) {
    int idx = blockIdx.x * 256 + threadIdx.x;
    int l = idx >> 16, n = (idx >> 8) & 255, k = idx & 255;
    float v = 0.f;
    if (k < BIN)
        v = (n < 128) ? Wbs[(size_t)l * BIN * HH + k * 128 + n]
                      : Wbn[(size_t)l * BIN * HH + k * 128 + (n - 128)];
    __nv_bfloat16 h, lo;
    bf16_split(v, h, lo);
    g_Whi[idx] = h;
    g_Wlo[idx] = lo;
    g_Wf[(((size_t)l * 256) + k) * 256 + n] = v;
}

// ---------------- prep: fill z/in6/pad cols [128,208) of all 4 A buffers ---------
__global__ void __launch_bounds__(256)
prep_kernel(const float* __restrict__ z,
            const float* __restrict__ vert,
            const float* __restrict__ vpot) {
    long long idx = (long long)blockIdx.x * 256 + threadIdx.x;
    if (idx >= 4LL * NN * 40) return;
    int t = (int)(idx % 40);
    long long r = idx / 40;
    int n = (int)(r % NN);
    int l = (int)(r / NN);
    int c = 128 + t * 2;
    float v0, v1;
    if (c < 192) {
        float2 zv = *(const float2*)(z + ((size_t)l * NN + n) * 64 + (c - 128));
        v0 = zv.x; v1 = zv.y;
    } else if (c < 198) {
        int j0 = c - 192, j1 = c - 191;
        v0 = (j0 < 3) ? vert[n * 3 + j0] : vpot[n * 3 + j0 - 3];
        v1 = (j1 < 3) ? vert[n * 3 + j1] : vpot[n * 3 + j1 - 3];
    } else {
        v0 = 0.f; v1 = 0.f;
    }
    __nv_bfloat16 h[2], lo[2];
    bf16_split(v0, h[0], lo[0]);
    bf16_split(v1, h[1], lo[1]);
    size_t base = ((size_t)l * NN + n) * 256 + c;
    *(uint32_t*)(g_Ahi + base) = *(const uint32_t*)h;
    *(uint32_t*)(g_Alo + base) = *(const uint32_t*)lo;
}

// ---------------- layer 0 GEMM: 32 nodes per block ----------------
__global__ void __launch_bounds__(256)
l0_gemm_kernel(const float* __restrict__ vert,
               const float* __restrict__ vpot,
               const float* __restrict__ W0s,
               const float* __restrict__ W0n) {
    __shared__ float xi[32][6];
    int t = threadIdx.x;
    int n0 = blockIdx.x * 32;
    if (t < 192) {
        int i = t / 6, k = t % 6;
        int n = n0 + i;
        xi[i][k] = (k < 3) ? vert[n * 3 + k] : vpot[n * 3 + (k - 3)];
    }
    __syncthreads();
    uint64_t pel = pol_evict_last();
    uint64_t pef = pol_evict_first();
    int c = t;
    const float* B = (c < 128) ? (W0s + c) : (W0n + (c - 128));
    float w0 = B[0], w1 = B[HH], w2 = B[2 * HH], w3 = B[3 * HH], w4 = B[4 * HH], w5 = B[5 * HH];
#pragma unroll 4
    for (int i = 0; i < 32; i++) {
        float acc = w0 * xi[i][0] + w1 * xi[i][1] + w2 * xi[i][2] +
                    w3 * xi[i][3] + w4 * xi[i][4] + w5 * xi[i][5];
        int n = n0 + i;
        if (c < 128) stg_hint_f(g_ts + (size_t)n * 128 + c, acc, pef);
        else         stg_hint_f(g_tn + (size_t)n * 128 + (c - 128), acc, pel);
    }
}

// ---------------- combine (body): agg+bias+relu -> feat cols of buffer[layer] ----
__global__ void __launch_bounds__(256)
combine_body_kernel(const float* __restrict__ bias, int layer) {
    uint64_t pel = pol_evict_last();
    uint64_t pef = pol_evict_first();
    int gw = (blockIdx.x * blockDim.x + threadIdx.x) >> 5;
    int lane = threadIdx.x & 31;
    if (gw >= NN) return;
    int n = gw;
    int s0 = g_off[n], s1 = g_off[n + 1];
    float4 acc = gather_agg(g_tn, s0, s1, lane, pel);
    float inv = 1.0f / (float)max(s1 - s0, 1);
    float4 ts = ldg_hint_f4((const float4*)(g_ts + (size_t)n * 128) + lane, pef);
    float4 b4 = ((const float4*)bias)[lane];
    float o[4];
    o[0] = fmaxf(ts.x + acc.x * inv + b4.x, 0.f);
    o[1] = fmaxf(ts.y + acc.y * inv + b4.y, 0.f);
    o[2] = fmaxf(ts.z + acc.z * inv + b4.z, 0.f);
    o[3] = fmaxf(ts.w + acc.w * inv + b4.w, 0.f);
    __nv_bfloat16 h[4], l[4];
#pragma unroll
    for (int j = 0; j < 4; j++) bf16_split(o[j], h[j], l[j]);
    size_t base = ((size_t)layer * NN + n) * 256 + lane * 4;
    *(uint2*)(g_Ahi + base) = *(const uint2*)h;
    *(uint2*)(g_Alo + base) = *(const uint2*)l;
}

// ---------------- combine (head): agg+bias+relu + fused head GEMM -> g_q --------
__global__ void __launch_bounds__(256)
combine_head_kernel(const float* __restrict__ bias,
                    const float* __restrict__ Wls,
                    const float* __restrict__ Wln) {
    __shared__ float Bs[128][6];
    int tid = threadIdx.x;
    for (int i = tid; i < 128 * 6; i += 256) {
        int k = i / 6, c = i % 6;
        Bs[k][c] = (c < 3) ? Wls[k * 3 + c] : Wln[k * 3 + (c - 3)];
    }
    __syncthreads();
    uint64_t pel = pol_evict_last();
    uint64_t pef = pol_evict_first();
    int gw = (blockIdx.x * blockDim.x + tid) >> 5;
    int lane = tid & 31;
    if (gw >= NN) return;
    int n = gw;
    int s0 = g_off[n], s1 = g_off[n + 1];
    float4 acc = gather_agg(g_tn, s0, s1, lane, pel);
    float inv = 1.0f / (float)max(s1 - s0, 1);
    float4 ts = ldg_hint_f4((const float4*)(g_ts + (size_t)n * 128) + lane, pef);
    float4 b4 = ((const float4*)bias)[lane];
    float o0 = fmaxf(ts.x + acc.x * inv + b4.x, 0.f);
    float o1 = fmaxf(ts.y + acc.y * inv + b4.y, 0.f);
    float o2 = fmaxf(ts.z + acc.z * inv + b4.z, 0.f);
    float o3 = fmaxf(ts.w + acc.w * inv + b4.w, 0.f);
    float p[6];
#pragma unroll
    for (int j = 0; j < 6; j++)
        p[j] = o0 * Bs[lane * 4 + 0][j] + o1 * Bs[lane * 4 + 1][j] +
               o2 * Bs[lane * 4 + 2][j] + o3 * Bs[lane * 4 + 3][j];
#pragma unroll
    for (int off = 16; off > 0; off >>= 1) {
#pragma unroll
        for (int j = 0; j < 6; j++)
            p[j] += __shfl_xor_sync(0xffffffff, p[j], off);
    }
    if (lane == 0) {
#pragma unroll
        for (int j = 0; j < 6; j++)
            g_q[(size_t)n * 6 + j] = p[j];
    }
}

// ---------------- body GEMM: tcgen05 (K=208 trimmed), SIMT fallback ----------
#define ST_BYTES 98304
#define SMEM_TILES 1024
#define GEMM_SMEM (SMEM_TILES + 2 * ST_BYTES)

__global__ void __launch_bounds__(256, 1)
tc_gemm_kernel(int layer) {
#if TC_OK
    extern __shared__ char smem[];
    uint32_t sb = smem_to_u32(smem);
    int tid = threadIdx.x;
    int wid = tid >> 5;
    int row0 = blockIdx.x * 128;
    uint64_t pel = pol_evict_last();
    uint64_t pef = pol_evict_first();

    if (wid == 0) {
        TCGEN05_ALLOC(sb, 256);
        TCGEN05_RELINQ();
    }
    if (tid == 0) {
        MBARRIER_INIT(sb + 8, 1);
        MBARRIER_INIT(sb + 16, 1);
    }
    __syncthreads();
    uint32_t tmem;
    asm volatile("ld.shared.b32 %0, [%1];" : "=r"(tmem) : "r"(sb));

    const __nv_bfloat16* Ah_g = g_Ahi + (size_t)layer * NN * 256;
    const __nv_bfloat16* Al_g = g_Alo + (size_t)layer * NN * 256;
    const __nv_bfloat16* Wh = g_Whi + (size_t)layer * 65536;
    const __nv_bfloat16* Wl = g_Wlo + (size_t)layer * 65536;

    auto load_stage = [&](int kc, int st, bool full) {
        char* base = smem + SMEM_TILES + st * ST_BYTES;
        int c0 = kc * 64;
        if (full) {
#pragma unroll
            for (int i = 0; i < 4; i++) {
                int u = tid + i * 256;
                int m = u >> 3, j = u & 7;
                int n = row0 + m;
                uint4 vh = make_uint4(0u, 0u, 0u, 0u), vl = vh;
                if (n < NN) {
                    vh = ldg_hint_u4(Ah_g + (size_t)n * 256 + c0 + j * 8, pef);
                    vl = ldg_hint_u4(Al_g + (size_t)n * 256 + c0 + j * 8, pef);
                }
                uint32_t off = SMEM_SWIZZLE_128B((uint32_t)(m * 128 + j * 16));
                *(uint4*)(base + off) = vh;
                *(uint4*)(base + 16384 + off) = vl;
            }
#pragma unroll
            for (int i = 0; i < 8; i++) {
                int u = tid + i * 256;
                int r = u >> 3, j = u & 7;
                uint4 vh = ldg_hint_u4(Wh + (size_t)r * 256 + c0 + j * 8, pel);
                uint4 vl = ldg_hint_u4(Wl + (size_t)r * 256 + c0 + j * 8, pel);
                uint32_t off = SMEM_SWIZZLE_128B((uint32_t)(r * 128 + j * 16));
                *(uint4*)(base + 32768 + off) = vh;
                *(uint4*)(base + 65536 + off) = vl;
            }
        } else {
            {
                int m = tid >> 1, j = tid & 1;
                int n = row0 + m;
                uint4 vh = make_uint4(0u, 0u, 0u, 0u), vl = vh;
                if (n < NN) {
                    vh = ldg_hint_u4(Ah_g + (size_t)n * 256 + c0 + j * 8, pef);
                    vl = ldg_hint_u4(Al_g + (size_t)n * 256 + c0 + j * 8, pef);
                }
                uint32_t off = SMEM_SWIZZLE_128B((uint32_t)(m * 128 + j * 16));
                *(uint4*)(base + off) = vh;
                *(uint4*)(base + 16384 + off) = vl;
            }
#pragma unroll
            for (int i = 0; i < 2; i++) {
                int u = tid + i * 256;
                int r = u >> 1, j = u & 1;
                uint4 vh = ldg_hint_u4(Wh + (size_t)r * 256 + c0 + j * 8, pel);
                uint4 vl = ldg_hint_u4(Wl + (size_t)r * 256 + c0 + j * 8, pel);
                uint32_t off = SMEM_SWIZZLE_128B((uint32_t)(r * 128 + j * 16));
                *(uint4*)(base + 32768 + off) = vh;
                *(uint4*)(base + 65536 + off) = vl;
            }
        }
    };

    load_stage(0, 0, true);
    FENCE_ASYNC();
    __syncthreads();

    for (int c = 0; c < 4; c++) {
        int st = c & 1;
        int nk = (c < 3) ? 4 : 1;
        if (wid == 0 && elect_one_pred()) {
            uint32_t tb = sb + SMEM_TILES + st * ST_BYTES;
            uint64_t ah = make_desc(tb);
            uint64_t al = make_desc(tb + 16384);
            uint64_t bh = make_desc(tb + 32768);
            uint64_t bl = make_desc(tb + 65536);
            for (int k = 0; k < nk; k++) {
                bool en = !(c == 0 && k == 0);
                mma_bf16_ss(tmem,       ah + k * 2, bh + k * 2,        MMA_IDESC, en);
                mma_bf16_ss(tmem,       ah + k * 2, bl + k * 2,        MMA_IDESC, true);
                mma_bf16_ss(tmem,       al + k * 2, bh + k * 2,        MMA_IDESC, true);
                mma_bf16_ss(tmem + 128, ah + k * 2, bh + 1024 + k * 2, MMA_IDESC, en);
                mma_bf16_ss(tmem + 128, ah + k * 2, bl + 1024 + k * 2, MMA_IDESC, true);
                mma_bf16_ss(tmem + 128, al + k * 2, bh + 1024 + k * 2, MMA_IDESC, true);
            }
            TCGEN05_COMMIT(sb + 8 + 8 * st);
        }
        if (c < 3) {
            if (c >= 1) MBARRIER_WAIT_PARITY(sb + 8 + 8 * ((c + 1) & 1), 0);
            load_stage(c + 1, st ^ 1, (c + 1) < 3);
            FENCE_ASYNC();
        }
        __syncthreads();
    }

    MBARRIER_WAIT_PARITY(sb + 8, 1);
    MBARRIER_WAIT_PARITY(sb + 16, 1);
    TCGEN05_FENCE_AFTER();

    // epilogue: all 8 warps drain TMEM (wid%4 = row subpartition, wid/4 = col half)
    {
        int lane = tid & 31;
        int sub = wid & 3;
        int half = wid >> 2;
        int n = row0 + sub * 32 + lane;
        int cb0 = half * 128;
#pragma unroll
        for (int cb = 0; cb < 128; cb += 32) {
            uint32_t r[32];
            TCGEN05_LD_X32(r, tmem + cb0 + cb);
            TCGEN05_WAIT_LD();
            if (n < NN) {
                float* dst = (half == 0 ? g_ts : g_tn) + (size_t)n * 128 + cb;
                uint64_t pol = (half == 0) ? pef : pel;
#pragma unroll
                for (int j = 0; j < 32; j += 4)
                    stg_hint_u4(dst + j, make_uint4(r[j], r[j + 1], r[j + 2], r[j + 3]), pol);
            }
        }
        TCGEN05_FENCE_BEFORE();
    }
    __syncthreads();
    if (wid == 0) TCGEN05_DEALLOC(tmem, 256);
#else
    // ------- SIMT f32x2 fallback -------
    extern __shared__ char smem[];
    float (*As)[16][132] = reinterpret_cast<float(*)[16][132]>(smem);
    float (*Bs)[16][128] = reinterpret_cast<float(*)[16][128]>(smem + 2 * 16 * 132 * 4);

    const int tid = threadIdx.x;
    const int tx = tid & 15;
    const int ty = tid >> 4;
    const int row0 = blockIdx.x * 128;
    const float* Wf = g_Wf + (size_t)layer * 65536;
    const __nv_bfloat16* Ah_g = g_Ahi + (size_t)layer * NN * 256;
    const __nv_bfloat16* Al_g = g_Alo + (size_t)layer * NN * 256;

    for (int half = 0; half < 2; half++) {
        const int col0 = half * 128;
        unsigned long long acc[8][4];
#pragma unroll
        for (int i = 0; i < 8; i++)
#pragma unroll
            for (int j = 0; j < 4; j++) acc[i][j] = 0ull;

        float ra[8], rb[8];
        auto loadA = [&](int kt, float* r) {
            int kbase = kt * 16;
#pragma unroll
            for (int j = 0; j < 8; j++) {
                int l = tid + j * 256;
                int m = l >> 4, kk = l & 15;
                int n = row0 + m;
                int k = kbase + kk;
                float v = 0.f;
                if (n < NN)
                    v = __bfloat162float(Ah_g[(size_t)n * 256 + k]) +
                        __bfloat162float(Al_g[(size_t)n * 256 + k]);
                r[j] = v;
            }
        };
        auto loadB = [&](int kt, float* r) {
            int kbase = kt * 16;
#pragma unroll
            for (int j = 0; j < 8; j++) {
                int l = tid + j * 256;
                int c = l & 127;
                int k = kbase + (l >> 7);
                r[j] = Wf[(size_t)k * 256 + col0 + c];
            }
        };
        auto storeA = [&](int st, const float* r) {
#pragma unroll
            for (int j = 0; j < 8; j++) {
                int l = tid + j * 256;
                As[st][l & 15][l >> 4] = r[j];
            }
        };
        auto storeB = [&](int st, const float* r) {
#pragma unroll
            for (int j = 0; j < 8; j++) {
                int l = tid + j * 256;
                Bs[st][l >> 7][l & 127] = r[j];
            }
        };

        loadA(0, ra); loadB(0, rb);
        storeA(0, ra); storeB(0, rb);
        __syncthreads();

        for (int kt = 0; kt < 13; kt++) {
            int cur = kt & 1;
            if (kt < 12) { loadA(kt + 1, ra); loadB(kt + 1, rb); }
#pragma unroll
            for (int kk = 0; kk < 16; kk++) {
                float4 a0 = *(const float4*)&As[cur][kk][ty * 8];
                float4 a1 = *(const float4*)&As[cur][kk][ty * 8 + 4];
                ulonglong2 b0 = *(const ulonglong2*)&Bs[cur][kk][tx * 4];
                ulonglong2 b1 = *(const ulonglong2*)&Bs[cur][kk][64 + tx * 4];
                unsigned long long ad[8];
                ad[0] = pack2(a0.x, a0.x); ad[1] = pack2(a0.y, a0.y);
                ad[2] = pack2(a0.z, a0.z); ad[3] = pack2(a0.w, a0.w);
                ad[4] = pack2(a1.x, a1.x); ad[5] = pack2(a1.y, a1.y);
                ad[6] = pack2(a1.z, a1.z); ad[7] = pack2(a1.w, a1.w);
#pragma unroll
                for (int i = 0; i < 8; i++) {
                    acc[i][0] = fma2(ad[i], b0.x, acc[i][0]);
                    acc[i][1] = fma2(ad[i], b0.y, acc[i][1]);
                    acc[i][2] = fma2(ad[i], b1.x, acc[i][2]);
                    acc[i][3] = fma2(ad[i], b1.y, acc[i][3]);
                }
            }
            if (kt < 12) { storeA(cur ^ 1, ra); storeB(cur ^ 1, rb); }
            __syncthreads();
        }

#pragma unroll
        for (int i = 0; i < 8; i++) {
            int n = row0 + ty * 8 + i;
            if (n < NN) {
                float* base = (half == 0 ? g_ts : g_tn) + (size_t)n * 128;
                ulonglong2 v0; v0.x = acc[i][0]; v0.y = acc[i][1];
                ulonglong2 v1; v1.x = acc[i][2]; v1.y = acc[i][3];
                *(ulonglong2*)(base + tx * 4) = v0;
                *(ulonglong2*)(base + 64 + tx * 4) = v1;
            }
        }
        __syncthreads();
    }
#endif
}

// ---------------- final combine ----------------
__global__ void final_combine_kernel(const float* __restrict__ bl,
                                     float* __restrict__ out) {
    int n = blockIdx.x * blockDim.x + threadIdx.x;
    if (n >= NN) return;
    int s0 = g_off[n], s1 = g_off[n + 1];
    float a0 = 0.f, a1 = 0.f, a2 = 0.f;
    for (int e = s0; e < s1; e++) {
        int s = g_csr[e];
        a0 += g_q[(size_t)s * 6 + 3];
        a1 += g_q[(size_t)s * 6 + 4];
        a2 += g_q[(size_t)s * 6 + 5];
    }
    float inv = 1.0f / (float)max(s1 - s0, 1);
    out[n * 3 + 0] = g_q[(size_t)n * 6 + 0] + a0 * inv + bl[0];
    out[n * 3 + 1] = g_q[(size_t)n * 6 + 1] + a1 * inv + bl[1];
    out[n * 3 + 2] = g_q[(size_t)n * 6 + 2] + a2 * inv + bl[2];
}

// ---------------- launch ----------------
extern "C" void kernel_launch(void* const* d_in, const int* in_sizes, int n_in,
                              void* d_out, int out_size) {
    const float* vert = (const float*)d_in[0];
    const void*  edges = d_in[1];
    const float* vpot = (const float*)d_in[2];
    const float* z    = (const float*)d_in[3];
    const float* W0s  = (const float*)d_in[4];
    const float* W0n  = (const float*)d_in[5];
    const float* b0   = (const float*)d_in[6];
    const float* Wbs  = (const float*)d_in[7];
    const float* Wbn  = (const float*)d_in[8];
    const float* bb   = (const float*)d_in[9];
    const float* Wls  = (const float*)d_in[10];
    const float* Wln  = (const float*)d_in[11];
    const float* bl   = (const float*)d_in[12];
    float* out = (float*)d_out;

    static cudaStream_t sB = nullptr;
    static cudaEvent_t evFork = nullptr, evJoin = nullptr;
    static bool attr_set = false;
    if (!attr_set) {
        cudaFuncSetAttribute(tc_gemm_kernel, cudaFuncAttributeMaxDynamicSharedMemorySize, GEMM_SMEM);
        cudaStreamCreateWithFlags(&sB, cudaStreamNonBlocking);
        cudaEventCreateWithFlags(&evFork, cudaEventDisableTiming);
        cudaEventCreateWithFlags(&evJoin, cudaEventDisableTiming);
        attr_set = true;
    }

    // ---- fork: prep chain on sB, CSR chain on default stream ----
    cudaEventRecord(evFork, 0);
    cudaStreamWaitEvent(sB, evFork, 0);

    wconv_kernel<<<1024, 256, 0, sB>>>(Wbs, Wbn);
    prep_kernel<<<(int)((4LL * NN * 40 + 255) / 256), 256, 0, sB>>>(z, vert, vpot);
    l0_gemm_kernel<<<NN / 32, 256, 0, sB>>>(vert, vpot, W0s, W0n);
    cudaEventRecord(evJoin, sB);

    // default stream: CSR build
    zero_counts_kernel<<<(NN + 1023) / 1024, 1024>>>(edges);
    count_kernel<<<(EE + 255) / 256, 256>>>(edges);
    scan_block_kernel<<<SCAN_BLOCKS, 1024>>>();
    scan_tops_kernel<<<1, 128>>>();
    scan_add_kernel<<<SCAN_BLOCKS, 1024>>>();
    scatter_kernel<<<(EE + 255) / 256, 256>>>(edges);

    cudaStreamWaitEvent(0, evJoin, 0);

    // layer 0 combine -> A buffer 0
    combine_body_kernel<<<(NN * 32 + 255) / 256, 256>>>(b0, 0);

    // 4 body layers
    for (int i = 0; i < 4; i++) {
        tc_gemm_kernel<<<MTILES, 256, GEMM_SMEM>>>(i);
        if (i < 3)
            combine_body_kernel<<<(NN * 32 + 255) / 256, 256>>>(bb + i * HH, i + 1);
        else
            combine_head_kernel<<<(NN * 32 + 255) / 256, 256>>>(bb + 3 * HH, Wls, Wln);
    }

    // head
    final_combine_kernel<<<(NN + 255) / 256, 256>>>(bl, out);
}

// round 14
// speedup vs baseline: 1.0411x; 1.0411x over previous
#include <cuda_runtime.h>
#include <cuda_bf16.h>
#include <cstdint>

#define NN 100000
#define EE 600000
#define HH 128
#define ZZ 64
#define BIN 198
#define SCAN_BLOCKS ((NN + 1023) / 1024)   // 98
#define MTILES ((NN + 127) / 128)          // 782

// ---------------- device scratch (no allocations allowed) ----------------
__device__ int   g_i64;
__device__ int   g_counts[NN];
__device__ int   g_off[NN + 1];
__device__ int   g_cursor[NN];
__device__ int   g_csr[EE];
__device__ int   g_bsums[SCAN_BLOCKS];
__device__ int   g_bsum_ex[SCAN_BLOCKS];
__device__ float g_ts[(size_t)NN * 128];               // GEMM out, s-half (streamed)
__device__ float g_tn[(size_t)NN * 128];               // GEMM out, n-half (gathered; L2-hot)
__device__ float g_q[(size_t)NN * 6];                  // head per-node outputs
__device__ __nv_bfloat16 g_Ahi[(size_t)4 * NN * 256];  // per-layer concat A, hi part
__device__ __nv_bfloat16 g_Alo[(size_t)4 * NN * 256];  // lo part
__device__ __nv_bfloat16 g_Whi[4 * 256 * 256];         // [layer][n(256)][k(256)]
__device__ __nv_bfloat16 g_Wlo[4 * 256 * 256];
__device__ float g_Wf[4 * 256 * 256];                  // fp32 [l][k][n] (fallback path)

// ---------------- arch feature gate ----------------
#if defined(__CUDA_ARCH_FEAT_SM103_ALL) || defined(__CUDA_ARCH_FEAT_SM100_ALL) || \
    defined(__CUDA_ARCH_FEAT_SM101_ALL) || defined(__CUDA_ARCH_FEAT_SM110_ALL)
#define TC_OK 1
#else
#define TC_OK 0
#endif

// ---------------- L2 policy-based cache hints ----------------
__device__ __forceinline__ uint64_t pol_evict_last() {
    uint64_t p;
    asm("createpolicy.fractional.L2::evict_last.b64 %0, 1.0;" : "=l"(p));
    return p;
}
__device__ __forceinline__ uint64_t pol_evict_first() {
    uint64_t p;
    asm("createpolicy.fractional.L2::evict_first.b64 %0, 1.0;" : "=l"(p));
    return p;
}
__device__ __forceinline__ float4 ldg_hint_f4(const float4* p, uint64_t pol) {
    float4 v;
    asm volatile("ld.global.nc.L2::cache_hint.v4.f32 {%0,%1,%2,%3}, [%4], %5;"
                 : "=f"(v.x), "=f"(v.y), "=f"(v.z), "=f"(v.w) : "l"(p), "l"(pol));
    return v;
}
__device__ __forceinline__ uint4 ldg_hint_u4(const void* p, uint64_t pol) {
    uint4 v;
    asm volatile("ld.global.nc.L2::cache_hint.v4.b32 {%0,%1,%2,%3}, [%4], %5;"
                 : "=r"(v.x), "=r"(v.y), "=r"(v.z), "=r"(v.w) : "l"(p), "l"(pol));
    return v;
}
__device__ __forceinline__ void stg_hint_u4(void* p, uint4 v, uint64_t pol) {
    asm volatile("st.global.L2::cache_hint.v4.b32 [%0], {%1,%2,%3,%4}, %5;"
                 :: "l"(p), "r"(v.x), "r"(v.y), "r"(v.z), "r"(v.w), "l"(pol) : "memory");
}
__device__ __forceinline__ void stg_hint_f(float* p, float v, uint64_t pol) {
    asm volatile("st.global.L2::cache_hint.f32 [%0], %1, %2;"
                 :: "l"(p), "f"(v), "l"(pol) : "memory");
}

// ---------------- PTX helpers ----------------
__device__ __forceinline__ uint32_t elect_one_pred() {
    uint32_t pred;
    asm volatile("{\n\t.reg .pred p;\n\telect.sync _|p, 0xFFFFFFFF;\n\tselp.b32 %0, 1, 0, p;\n\t}"
                 : "=r"(pred));
    return pred;
}
__device__ __forceinline__ uint32_t smem_to_u32(const void* p) {
    uint32_t a;
    asm("{ .reg .u64 t; cvta.to.shared.u64 t, %1; cvt.u32.u64 %0, t; }" : "=r"(a) : "l"(p));
    return a;
}
#define SMEM_SWIZZLE_128B(x) ((x) ^ (((x) >> 3) & 0x70))

#define TCGEN05_ALLOC(sa, n) \
    asm volatile("tcgen05.alloc.cta_group::1.sync.aligned.shared::cta.b32 [%0], %1;" \
                 :: "r"((uint32_t)(sa)), "r"((uint32_t)(n)) : "memory")
#define TCGEN05_DEALLOC(t, n) \
    asm volatile("tcgen05.dealloc.cta_group::1.sync.aligned.b32 %0, %1;" :: "r"(t), "r"(n))
#define TCGEN05_RELINQ() \
    asm volatile("tcgen05.relinquish_alloc_permit.cta_group::1.sync.aligned;")
#define TCGEN05_COMMIT(mb) \
    asm volatile("tcgen05.commit.cta_group::1.mbarrier::arrive::one.shared::cluster.b64 [%0];" \
                 :: "r"((uint32_t)(mb)) : "memory")
#define TCGEN05_FENCE_AFTER() asm volatile("tcgen05.fence::after_thread_sync;" ::: "memory")
#define TCGEN05_FENCE_BEFORE() asm volatile("tcgen05.fence::before_thread_sync;" ::: "memory")
#define TCGEN05_WAIT_LD() asm volatile("tcgen05.wait::ld.sync.aligned;" ::: "memory")
#define FENCE_ASYNC() asm volatile("fence.proxy.async.shared::cta;" ::: "memory")
#define MBARRIER_INIT(mb, c) \
    asm volatile("mbarrier.init.shared.b64 [%0], %1;" :: "r"((uint32_t)(mb)), "r"((uint32_t)(c)) : "memory")

#define MBARRIER_WAIT_PARITY(mb, ph) do { \
    uint32_t _m = (uint32_t)(mb), _p = (uint32_t)(ph), _d; \
    asm volatile("{\n\t.reg .pred p;\n\t" \
        "mbarrier.try_wait.parity.acquire.cta.shared::cta.b64 p, [%1], %2;\n\t" \
        "selp.b32 %0, 1, 0, p;\n\t}" : "=r"(_d) : "r"(_m), "r"(_p) : "memory"); \
    if (!_d) { \
        asm volatile("{\n\t.reg .pred P1;\n\t" \
            "WL_%=:\n\t" \
            "mbarrier.try_wait.parity.acquire.cta.shared::cta.b64 P1, [%0], %1, 0x989680;\n\t" \
            "@P1 bra.uni WD_%=;\n\tbra.uni WL_%=;\n\tWD_%=:\n\t}" \
            :: "r"(_m), "r"(_p) : "memory"); \
    } \
} while (0)

#define TCGEN05_LD_X32(r, ta) \
    asm volatile("tcgen05.ld.sync.aligned.32x32b.x32.b32 " \
        "{%0, %1, %2, %3, %4, %5, %6, %7, %8, %9, %10, %11, %12, %13, %14, %15, " \
        "%16, %17, %18, %19, %20, %21, %22, %23, %24, %25, %26, %27, %28, %29, %30, %31}, [%32];" \
        : "=r"((r)[0]), "=r"((r)[1]), "=r"((r)[2]), "=r"((r)[3]), "=r"((r)[4]), "=r"((r)[5]), \
          "=r"((r)[6]), "=r"((r)[7]), "=r"((r)[8]), "=r"((r)[9]), "=r"((r)[10]), "=r"((r)[11]), \
          "=r"((r)[12]), "=r"((r)[13]), "=r"((r)[14]), "=r"((r)[15]), "=r"((r)[16]), "=r"((r)[17]), \
          "=r"((r)[18]), "=r"((r)[19]), "=r"((r)[20]), "=r"((r)[21]), "=r"((r)[22]), "=r"((r)[23]), \
          "=r"((r)[24]), "=r"((r)[25]), "=r"((r)[26]), "=r"((r)[27]), "=r"((r)[28]), "=r"((r)[29]), \
          "=r"((r)[30]), "=r"((r)[31]) : "r"(ta))

#if TC_OK
__device__ __forceinline__ void mma_bf16_ss(uint32_t d, uint64_t a, uint64_t b,
                                            uint32_t idesc, bool en) {
    uint32_t e = en ? 1u : 0u;
    asm volatile(
        "{\n\t.reg .pred p;\n\tsetp.ne.u32 p, %5, 0;\n\t"
        "tcgen05.mma.cta_group::1.kind::f16 [%0], %1, %2, %3, {%4, %4, %4, %4}, p;\n\t}"
        :: "r"(d), "l"(a), "l"(b), "r"(idesc), "r"(0u), "r"(e) : "memory");
}
#endif

__device__ __forceinline__ uint64_t make_desc(uint32_t addr) {
    const uint64_t base = (2ull << 61) | (1ull << 46) | (64ull << 32) | (1ull << 16);
    return base | ((uint64_t)(addr >> 4) & 0x3FFF);
}

#define MMA_IDESC ((1u << 4) | (1u << 7) | (1u << 10) | ((128u / 8) << 17) | ((128u / 16) << 24))

__device__ __forceinline__ int2 edge_pair(const void* edges, int e) {
    if (g_i64) {
        longlong2 v = ((const longlong2*)edges)[e];
        return make_int2((int)v.x, (int)v.y);
    }
    return ((const int2*)edges)[e];
}
__device__ __forceinline__ void bf16_split(float x, __nv_bfloat16& h, __nv_bfloat16& l) {
    h = __float2bfloat16(x);
    l = __float2bfloat16(x - __bfloat162float(h));
}
__device__ __forceinline__ unsigned long long pack2(float x, float y) {
    unsigned long long d;
    asm("mov.b64 %0, {%1, %2};" : "=l"(d) : "f"(x), "f"(y));
    return d;
}
__device__ __forceinline__ unsigned long long fma2(unsigned long long a,
                                                   unsigned long long b,
                                                   unsigned long long c) {
    unsigned long long d;
    asm("fma.rn.f32x2 %0, %1, %2, %3;" : "=l"(d) : "l"(a), "l"(b), "l"(c));
    return d;
}

// ---------------- CSR construction ----------------
__global__ void zero_counts_kernel(const void* edges) {
    int i = blockIdx.x * blockDim.x + threadIdx.x;
    if (i < NN) g_counts[i] = 0;
    if (blockIdx.x == 0 && threadIdx.x < 32) {      // fused int64 detection
        const long long* p = (const long long*)edges;
        long long v = p[threadIdx.x];
        bool ok = (v >= 0 && v < NN);
        unsigned m = __ballot_sync(0xffffffff, ok);
        if (threadIdx.x == 0) g_i64 = (m == 0xffffffffu) ? 1 : 0;
    }
}
__global__ void count_kernel(const void* edges) {
    int e = blockIdx.x * blockDim.x + threadIdx.x;
    if (e < EE) atomicAdd(&g_counts[edge_pair(edges, e).y], 1);
}
__global__ void scan_block_kernel() {
    __shared__ int s[1024];
    int t = threadIdx.x;
    int i = blockIdx.x * 1024 + t;
    int v = (i < NN) ? g_counts[i] : 0;
    s[t] = v;
    __syncthreads();
#pragma unroll
    for (int d = 1; d < 1024; d <<= 1) {
        int x = (t >= d) ? s[t - d] : 0;
        __syncthreads();
        s[t] += x;
        __syncthreads();
    }
    if (i < NN) g_off[i] = s[t] - v;
    if (t == 1023) g_bsums[blockIdx.x] = s[1023];
}
__global__ void scan_tops_kernel() {
    __shared__ int s[128];
    int t = threadIdx.x;
    int v = (t < SCAN_BLOCKS) ? g_bsums[t] : 0;
    s[t] = v;
    __syncthreads();
#pragma unroll
    for (int d = 1; d < 128; d <<= 1) {
        int x = (t >= d) ? s[t - d] : 0;
        __syncthreads();
        s[t] += x;
        __syncthreads();
    }
    if (t < SCAN_BLOCKS) g_bsum_ex[t] = s[t] - v;
}
__global__ void scan_add_kernel() {
    int i = blockIdx.x * 1024 + threadIdx.x;
    if (i < NN) {
        int o = g_off[i] + g_bsum_ex[blockIdx.x];
        g_off[i] = o;
        g_cursor[i] = o;
    }
    if (i == 0) g_off[NN] = EE;
}
__global__ void scatter_kernel(const void* edges) {
    int e = blockIdx.x * blockDim.x + threadIdx.x;
    if (e < EE) {
        int2 p = edge_pair(edges, e);
        g_csr[atomicAdd(&g_cursor[p.y], 1)] = p.x;
    }
}

// ---------------- weight transpose+split ----------------
__global__ void wconv_kernel(const float* __restrict__ Wbs, const float* __restrict__ Wbn) {
    int idx = blockIdx.x * 256 + threadIdx.x;   // 4*256*256
    int l = idx >> 16, n = (idx >> 8) & 255, k = idx & 255;
    float v = 0.f;
    if (k < BIN)
        v = (n < 128) ? Wbs[(size_t)l * BIN * HH + k * 128 + n]
                      : Wbn[(size_t)l * BIN * HH + k * 128 + (n - 128)];
    __nv_bfloat16 h, lo;
    bf16_split(v, h, lo);
    g_Whi[idx] = h;
    g_Wlo[idx] = lo;
    g_Wf[(((size_t)l * 256) + k) * 256 + n] = v;
}

// ---------------- prep: fill z/in6/pad cols [128,208) of all 4 A buffers ---------
__global__ void __launch_bounds__(256)
prep_kernel(const float* __restrict__ z,
            const float* __restrict__ vert,
            const float* __restrict__ vpot) {
    long long idx = (long long)blockIdx.x * 256 + threadIdx.x;   // 4*NN*40
    if (idx >= 4LL * NN * 40) return;
    int t = (int)(idx % 40);
    long long r = idx / 40;
    int n = (int)(r % NN);
    int l = (int)(r / NN);
    int c = 128 + t * 2;
    float v0, v1;
    if (c < 192) {
        float2 zv = *(const float2*)(z + ((size_t)l * NN + n) * 64 + (c - 128));
        v0 = zv.x; v1 = zv.y;
    } else if (c < 198) {
        int j0 = c - 192, j1 = c - 191;
        v0 = (j0 < 3) ? vert[n * 3 + j0] : vpot[n * 3 + j0 - 3];
        v1 = (j1 < 3) ? vert[n * 3 + j1] : vpot[n * 3 + j1 - 3];
    } else {
        v0 = 0.f; v1 = 0.f;
    }
    __nv_bfloat16 h[2], lo[2];
    bf16_split(v0, h[0], lo[0]);
    bf16_split(v1, h[1], lo[1]);
    size_t base = ((size_t)l * NN + n) * 256 + c;
    *(uint32_t*)(g_Ahi + base) = *(const uint32_t*)h;
    *(uint32_t*)(g_Alo + base) = *(const uint32_t*)lo;
}

// ---------------- layer 0 GEMM: 32 nodes per block ----------------
__global__ void __launch_bounds__(256)
l0_gemm_kernel(const float* __restrict__ vert,
               const float* __restrict__ vpot,
               const float* __restrict__ W0s,
               const float* __restrict__ W0n) {
    __shared__ float xi[32][6];
    int t = threadIdx.x;
    int n0 = blockIdx.x * 32;
    if (t < 192) {
        int i = t / 6, k = t % 6;
        int n = n0 + i;
        xi[i][k] = (k < 3) ? vert[n * 3 + k] : vpot[n * 3 + (k - 3)];
    }
    __syncthreads();
    uint64_t pel = pol_evict_last();
    uint64_t pef = pol_evict_first();
    int c = t;
    const float* B = (c < 128) ? (W0s + c) : (W0n + (c - 128));
    float w0 = B[0], w1 = B[HH], w2 = B[2 * HH], w3 = B[3 * HH], w4 = B[4 * HH], w5 = B[5 * HH];
#pragma unroll 4
    for (int i = 0; i < 32; i++) {
        float acc = w0 * xi[i][0] + w1 * xi[i][1] + w2 * xi[i][2] +
                    w3 * xi[i][3] + w4 * xi[i][4] + w5 * xi[i][5];
        int n = n0 + i;
        if (c < 128) stg_hint_f(g_ts + (size_t)n * 128 + c, acc, pef);
        else         stg_hint_f(g_tn + (size_t)n * 128 + (c - 128), acc, pel);
    }
}

// ---------------- combine (body): agg+bias+relu -> feat cols of buffer[layer] ----
__global__ void __launch_bounds__(256)
combine_body_kernel(const float* __restrict__ bias, int layer) {
    uint64_t pel = pol_evict_last();
    uint64_t pef = pol_evict_first();
    int gw = (blockIdx.x * blockDim.x + threadIdx.x) >> 5;
    int lane = threadIdx.x & 31;
    if (gw >= NN) return;
    int n = gw;
    int s0 = g_off[n], s1 = g_off[n + 1];
    float4 acc = make_float4(0.f, 0.f, 0.f, 0.f);
    int e = s0;
    for (; e + 4 <= s1; e += 4) {
        int i0 = g_csr[e], i1 = g_csr[e + 1], i2 = g_csr[e + 2], i3 = g_csr[e + 3];
        float4 v0 = ldg_hint_f4((const float4*)(g_tn + (size_t)i0 * 128) + lane, pel);
        float4 v1 = ldg_hint_f4((const float4*)(g_tn + (size_t)i1 * 128) + lane, pel);
        float4 v2 = ldg_hint_f4((const float4*)(g_tn + (size_t)i2 * 128) + lane, pel);
        float4 v3 = ldg_hint_f4((const float4*)(g_tn + (size_t)i3 * 128) + lane, pel);
        acc.x += (v0.x + v1.x) + (v2.x + v3.x);
        acc.y += (v0.y + v1.y) + (v2.y + v3.y);
        acc.z += (v0.z + v1.z) + (v2.z + v3.z);
        acc.w += (v0.w + v1.w) + (v2.w + v3.w);
    }
    for (; e < s1; e++) {
        int s = g_csr[e];
        float4 v = ldg_hint_f4((const float4*)(g_tn + (size_t)s * 128) + lane, pel);
        acc.x += v.x; acc.y += v.y; acc.z += v.z; acc.w += v.w;
    }
    float inv = 1.0f / (float)max(s1 - s0, 1);
    float4 ts = ldg_hint_f4((const float4*)(g_ts + (size_t)n * 128) + lane, pef);
    float4 b4 = ((const float4*)bias)[lane];
    float o[4];
    o[0] = fmaxf(ts.x + acc.x * inv + b4.x, 0.f);
    o[1] = fmaxf(ts.y + acc.y * inv + b4.y, 0.f);
    o[2] = fmaxf(ts.z + acc.z * inv + b4.z, 0.f);
    o[3] = fmaxf(ts.w + acc.w * inv + b4.w, 0.f);
    __nv_bfloat16 h[4], l[4];
#pragma unroll
    for (int j = 0; j < 4; j++) bf16_split(o[j], h[j], l[j]);
    size_t base = ((size_t)layer * NN + n) * 256 + lane * 4;
    *(uint2*)(g_Ahi + base) = *(const uint2*)h;
    *(uint2*)(g_Alo + base) = *(const uint2*)l;
}

// ---------------- combine (head): agg+bias+relu + fused head GEMM -> g_q --------
__global__ void __launch_bounds__(256)
combine_head_kernel(const float* __restrict__ bias,
                    const float* __restrict__ Wls,
                    const float* __restrict__ Wln) {
    __shared__ float Bs[128][6];
    int tid = threadIdx.x;
    for (int i = tid; i < 128 * 6; i += 256) {
        int k = i / 6, c = i % 6;
        Bs[k][c] = (c < 3) ? Wls[k * 3 + c] : Wln[k * 3 + (c - 3)];
    }
    __syncthreads();
    uint64_t pel = pol_evict_last();
    uint64_t pef = pol_evict_first();
    int gw = (blockIdx.x * blockDim.x + tid) >> 5;
    int lane = tid & 31;
    if (gw >= NN) return;
    int n = gw;
    int s0 = g_off[n], s1 = g_off[n + 1];
    float4 acc = make_float4(0.f, 0.f, 0.f, 0.f);
    int e = s0;
    for (; e + 4 <= s1; e += 4) {
        int i0 = g_csr[e], i1 = g_csr[e + 1], i2 = g_csr[e + 2], i3 = g_csr[e + 3];
        float4 v0 = ldg_hint_f4((const float4*)(g_tn + (size_t)i0 * 128) + lane, pel);
        float4 v1 = ldg_hint_f4((const float4*)(g_tn + (size_t)i1 * 128) + lane, pel);
        float4 v2 = ldg_hint_f4((const float4*)(g_tn + (size_t)i2 * 128) + lane, pel);
        float4 v3 = ldg_hint_f4((const float4*)(g_tn + (size_t)i3 * 128) + lane, pel);
        acc.x += (v0.x + v1.x) + (v2.x + v3.x);
        acc.y += (v0.y + v1.y) + (v2.y + v3.y);
        acc.z += (v0.z + v1.z) + (v2.z + v3.z);
        acc.w += (v0.w + v1.w) + (v2.w + v3.w);
    }
    for (; e < s1; e++) {
        int s = g_csr[e];
        float4 v = ldg_hint_f4((const float4*)(g_tn + (size_t)s * 128) + lane, pel);
        acc.x += v.x; acc.y += v.y; acc.z += v.z; acc.w += v.w;
    }
    float inv = 1.0f / (float)max(s1 - s0, 1);
    float4 ts = ldg_hint_f4((const float4*)(g_ts + (size_t)n * 128) + lane, pef);
    float4 b4 = ((const float4*)bias)[lane];
    float o0 = fmaxf(ts.x + acc.x * inv + b4.x, 0.f);
    float o1 = fmaxf(ts.y + acc.y * inv + b4.y, 0.f);
    float o2 = fmaxf(ts.z + acc.z * inv + b4.z, 0.f);
    float o3 = fmaxf(ts.w + acc.w * inv + b4.w, 0.f);
    float p[6];
#pragma unroll
    for (int j = 0; j < 6; j++)
        p[j] = o0 * Bs[lane * 4 + 0][j] + o1 * Bs[lane * 4 + 1][j] +
               o2 * Bs[lane * 4 + 2][j] + o3 * Bs[lane * 4 + 3][j];
#pragma unroll
    for (int off = 16; off > 0; off >>= 1) {
#pragma unroll
        for (int j = 0; j < 6; j++)
            p[j] += __shfl_xor_sync(0xffffffff, p[j], off);
    }
    if (lane == 0) {
#pragma unroll
        for (int j = 0; j < 6; j++)
            g_q[(size_t)n * 6 + j] = p[j];
    }
}

// ---------------- body GEMM: tcgen05 (K=208 trimmed), SIMT fallback ----------
#define ST_BYTES 98304
#define SMEM_TILES 1024
#define GEMM_SMEM (SMEM_TILES + 2 * ST_BYTES)   // 197632

__global__ void __launch_bounds__(256, 1)
tc_gemm_kernel(int layer) {
#if TC_OK
    extern __shared__ char smem[];
    uint32_t sb = smem_to_u32(smem);
    int tid = threadIdx.x;
    int wid = tid >> 5;
    int row0 = blockIdx.x * 128;
    uint64_t pel = pol_evict_last();
    uint64_t pef = pol_evict_first();

    if (wid == 0) {
        TCGEN05_ALLOC(sb, 256);
        TCGEN05_RELINQ();
    }
    if (tid == 0) {
        MBARRIER_INIT(sb + 8, 1);
        MBARRIER_INIT(sb + 16, 1);
    }
    __syncthreads();
    uint32_t tmem;
    asm volatile("ld.shared.b32 %0, [%1];" : "=r"(tmem) : "r"(sb));

    const __nv_bfloat16* Ah_g = g_Ahi + (size_t)layer * NN * 256;
    const __nv_bfloat16* Al_g = g_Alo + (size_t)layer * NN * 256;
    const __nv_bfloat16* Wh = g_Whi + (size_t)layer * 65536;
    const __nv_bfloat16* Wl = g_Wlo + (size_t)layer * 65536;

    auto load_stage = [&](int kc, int st, bool full) {
        char* base = smem + SMEM_TILES + st * ST_BYTES;
        int c0 = kc * 64;
        if (full) {
#pragma unroll
            for (int i = 0; i < 4; i++) {           // A (stream once)
                int u = tid + i * 256;
                int m = u >> 3, j = u & 7;
                int n = row0 + m;
                uint4 vh = make_uint4(0u, 0u, 0u, 0u), vl = vh;
                if (n < NN) {
                    vh = ldg_hint_u4(Ah_g + (size_t)n * 256 + c0 + j * 8, pef);
                    vl = ldg_hint_u4(Al_g + (size_t)n * 256 + c0 + j * 8, pef);
                }
                uint32_t off = SMEM_SWIZZLE_128B((uint32_t)(m * 128 + j * 16));
                *(uint4*)(base + off) = vh;
                *(uint4*)(base + 16384 + off) = vl;
            }
#pragma unroll
            for (int i = 0; i < 8; i++) {           // B (hot, reused by all CTAs)
                int u = tid + i * 256;
                int r = u >> 3, j = u & 7;
                uint4 vh = ldg_hint_u4(Wh + (size_t)r * 256 + c0 + j * 8, pel);
                uint4 vl = ldg_hint_u4(Wl + (size_t)r * 256 + c0 + j * 8, pel);
                uint32_t off = SMEM_SWIZZLE_128B((uint32_t)(r * 128 + j * 16));
                *(uint4*)(base + 32768 + off) = vh;
                *(uint4*)(base + 65536 + off) = vl;
            }
        } else {
            {
                int m = tid >> 1, j = tid & 1;
                int n = row0 + m;
                uint4 vh = make_uint4(0u, 0u, 0u, 0u), vl = vh;
                if (n < NN) {
                    vh = ldg_hint_u4(Ah_g + (size_t)n * 256 + c0 + j * 8, pef);
                    vl = ldg_hint_u4(Al_g + (size_t)n * 256 + c0 + j * 8, pef);
                }
                uint32_t off = SMEM_SWIZZLE_128B((uint32_t)(m * 128 + j * 16));
                *(uint4*)(base + off) = vh;
                *(uint4*)(base + 16384 + off) = vl;
            }
#pragma unroll
            for (int i = 0; i < 2; i++) {
                int u = tid + i * 256;
                int r = u >> 1, j = u & 1;
                uint4 vh = ldg_hint_u4(Wh + (size_t)r * 256 + c0 + j * 8, pel);
                uint4 vl = ldg_hint_u4(Wl + (size_t)r * 256 + c0 + j * 8, pel);
                uint32_t off = SMEM_SWIZZLE_128B((uint32_t)(r * 128 + j * 16));
                *(uint4*)(base + 32768 + off) = vh;
                *(uint4*)(base + 65536 + off) = vl;
            }
        }
    };

    load_stage(0, 0, true);
    FENCE_ASYNC();
    __syncthreads();

    for (int c = 0; c < 4; c++) {
        int st = c & 1;
        int nk = (c < 3) ? 4 : 1;
        if (wid == 0 && elect_one_pred()) {
            uint32_t tb = sb + SMEM_TILES + st * ST_BYTES;
            uint64_t ah = make_desc(tb);
            uint64_t al = make_desc(tb + 16384);
            uint64_t bh = make_desc(tb + 32768);
            uint64_t bl = make_desc(tb + 65536);
            for (int k = 0; k < nk; k++) {
                bool en = !(c == 0 && k == 0);
                mma_bf16_ss(tmem,       ah + k * 2, bh + k * 2,        MMA_IDESC, en);
                mma_bf16_ss(tmem,       ah + k * 2, bl + k * 2,        MMA_IDESC, true);
                mma_bf16_ss(tmem,       al + k * 2, bh + k * 2,        MMA_IDESC, true);
                mma_bf16_ss(tmem + 128, ah + k * 2, bh + 1024 + k * 2, MMA_IDESC, en);
                mma_bf16_ss(tmem + 128, ah + k * 2, bl + 1024 + k * 2, MMA_IDESC, true);
                mma_bf16_ss(tmem + 128, al + k * 2, bh + 1024 + k * 2, MMA_IDESC, true);
            }
            TCGEN05_COMMIT(sb + 8 + 8 * st);
        }
        if (c < 3) {
            if (c >= 1) MBARRIER_WAIT_PARITY(sb + 8 + 8 * ((c + 1) & 1), 0);
            load_stage(c + 1, st ^ 1, (c + 1) < 3);
            FENCE_ASYNC();
        }
        __syncthreads();
    }

    MBARRIER_WAIT_PARITY(sb + 8, 1);
    MBARRIER_WAIT_PARITY(sb + 16, 1);
    TCGEN05_FENCE_AFTER();

    if (wid < 4) {
        int lane = tid & 31;
        int n = row0 + wid * 32 + lane;
#pragma unroll
        for (int cb = 0; cb < 256; cb += 32) {
            uint32_t r[32];
            TCGEN05_LD_X32(r, tmem + cb);
            TCGEN05_WAIT_LD();
            if (n < NN) {
                if (cb < 128) {
                    float* dst = g_ts + (size_t)n * 128 + cb;
#pragma unroll
                    for (int j = 0; j < 32; j += 4)
                        stg_hint_u4(dst + j, make_uint4(r[j], r[j + 1], r[j + 2], r[j + 3]), pef);
                } else {
                    float* dst = g_tn + (size_t)n * 128 + (cb - 128);
#pragma unroll
                    for (int j = 0; j < 32; j += 4)
                        stg_hint_u4(dst + j, make_uint4(r[j], r[j + 1], r[j + 2], r[j + 3]), pel);
                }
            }
        }
        TCGEN05_FENCE_BEFORE();
    }
    __syncthreads();
    if (wid == 0) TCGEN05_DEALLOC(tmem, 256);
#else
    // ------- SIMT f32x2 fallback -------
    extern __shared__ char smem[];
    float (*As)[16][132] = reinterpret_cast<float(*)[16][132]>(smem);
    float (*Bs)[16][128] = reinterpret_cast<float(*)[16][128]>(smem + 2 * 16 * 132 * 4);

    const int tid = threadIdx.x;
    const int tx = tid & 15;
    const int ty = tid >> 4;
    const int row0 = blockIdx.x * 128;
    const float* Wf = g_Wf + (size_t)layer * 65536;
    const __nv_bfloat16* Ah_g = g_Ahi + (size_t)layer * NN * 256;
    const __nv_bfloat16* Al_g = g_Alo + (size_t)layer * NN * 256;

    for (int half = 0; half < 2; half++) {
        const int col0 = half * 128;
        unsigned long long acc[8][4];
#pragma unroll
        for (int i = 0; i < 8; i++)
#pragma unroll
            for (int j = 0; j < 4; j++) acc[i][j] = 0ull;

        float ra[8], rb[8];
        auto loadA = [&](int kt, float* r) {
            int kbase = kt * 16;
#pragma unroll
            for (int j = 0; j < 8; j++) {
                int l = tid + j * 256;
                int m = l >> 4, kk = l & 15;
                int n = row0 + m;
                int k = kbase + kk;
                float v = 0.f;
                if (n < NN)
                    v = __bfloat162float(Ah_g[(size_t)n * 256 + k]) +
                        __bfloat162float(Al_g[(size_t)n * 256 + k]);
                r[j] = v;
            }
        };
        auto loadB = [&](int kt, float* r) {
            int kbase = kt * 16;
#pragma unroll
            for (int j = 0; j < 8; j++) {
                int l = tid + j * 256;
                int c = l & 127;
                int k = kbase + (l >> 7);
                r[j] = Wf[(size_t)k * 256 + col0 + c];
            }
        };
        auto storeA = [&](int st, const float* r) {
#pragma unroll
            for (int j = 0; j < 8; j++) {
                int l = tid + j * 256;
                As[st][l & 15][l >> 4] = r[j];
            }
        };
        auto storeB = [&](int st, const float* r) {
#pragma unroll
            for (int j = 0; j < 8; j++) {
                int l = tid + j * 256;
                Bs[st][l >> 7][l & 127] = r[j];
            }
        };

        loadA(0, ra); loadB(0, rb);
        storeA(0, ra); storeB(0, rb);
        __syncthreads();

        for (int kt = 0; kt < 13; kt++) {
            int cur = kt & 1;
            if (kt < 12) { loadA(kt + 1, ra); loadB(kt + 1, rb); }
#pragma unroll
            for (int kk = 0; kk < 16; kk++) {
                float4 a0 = *(const float4*)&As[cur][kk][ty * 8];
                float4 a1 = *(const float4*)&As[cur][kk][ty * 8 + 4];
                ulonglong2 b0 = *(const ulonglong2*)&Bs[cur][kk][tx * 4];
                ulonglong2 b1 = *(const ulonglong2*)&Bs[cur][kk][64 + tx * 4];
                unsigned long long ad[8];
                ad[0] = pack2(a0.x, a0.x); ad[1] = pack2(a0.y, a0.y);
                ad[2] = pack2(a0.z, a0.z); ad[3] = pack2(a0.w, a0.w);
                ad[4] = pack2(a1.x, a1.x); ad[5] = pack2(a1.y, a1.y);
                ad[6] = pack2(a1.z, a1.z); ad[7] = pack2(a1.w, a1.w);
#pragma unroll
                for (int i = 0; i < 8; i++) {
                    acc[i][0] = fma2(ad[i], b0.x, acc[i][0]);
                    acc[i][1] = fma2(ad[i], b0.y, acc[i][1]);
                    acc[i][2] = fma2(ad[i], b1.x, acc[i][2]);
                    acc[i][3] = fma2(ad[i], b1.y, acc[i][3]);
                }
            }
            if (kt < 12) { storeA(cur ^ 1, ra); storeB(cur ^ 1, rb); }
            __syncthreads();
        }

#pragma unroll
        for (int i = 0; i < 8; i++) {
            int n = row0 + ty * 8 + i;
            if (n < NN) {
                float* base = (half == 0 ? g_ts : g_tn) + (size_t)n * 128;
                ulonglong2 v0; v0.x = acc[i][0]; v0.y = acc[i][1];
                ulonglong2 v1; v1.x = acc[i][2]; v1.y = acc[i][3];
                *(ulonglong2*)(base + tx * 4) = v0;
                *(ulonglong2*)(base + 64 + tx * 4) = v1;
            }
        }
        __syncthreads();
    }
#endif
}

// ---------------- final combine: out = q_s + agg(q_n)/deg + bl ----------------
__global__ void final_combine_kernel(const float* __restrict__ bl,
                                     float* __restrict__ out) {
    int n = blockIdx.x * blockDim.x + threadIdx.x;
    if (n >= NN) return;
    int s0 = g_off[n], s1 = g_off[n + 1];
    float a0 = 0.f, a1 = 0.f, a2 = 0.f;
    for (int e = s0; e < s1; e++) {
        int s = g_csr[e];
        a0 += g_q[(size_t)s * 6 + 3];
        a1 += g_q[(size_t)s * 6 + 4];
        a2 += g_q[(size_t)s * 6 + 5];
    }
    float inv = 1.0f / (float)max(s1 - s0, 1);
    out[n * 3 + 0] = g_q[(size_t)n * 6 + 0] + a0 * inv + bl[0];
    out[n * 3 + 1] = g_q[(size_t)n * 6 + 1] + a1 * inv + bl[1];
    out[n * 3 + 2] = g_q[(size_t)n * 6 + 2] + a2 * inv + bl[2];
}

// ---------------- launch ----------------
extern "C" void kernel_launch(void* const* d_in, const int* in_sizes, int n_in,
                              void* d_out, int out_size) {
    const float* vert = (const float*)d_in[0];
    const void*  edges = d_in[1];
    const float* vpot = (const float*)d_in[2];
    const float* z    = (const float*)d_in[3];
    const float* W0s  = (const float*)d_in[4];
    const float* W0n  = (const float*)d_in[5];
    const float* b0   = (const float*)d_in[6];
    const float* Wbs  = (const float*)d_in[7];
    const float* Wbn  = (const float*)d_in[8];
    const float* bb   = (const float*)d_in[9];
    const float* Wls  = (const float*)d_in[10];
    const float* Wln  = (const float*)d_in[11];
    const float* bl   = (const float*)d_in[12];
    float* out = (float*)d_out;

    static cudaStream_t sB = nullptr;
    static cudaEvent_t evFork = nullptr, evJoin = nullptr;
    static bool attr_set = false;
    if (!attr_set) {
        cudaFuncSetAttribute(tc_gemm_kernel, cudaFuncAttributeMaxDynamicSharedMemorySize, GEMM_SMEM);
        cudaStreamCreateWithFlags(&sB, cudaStreamNonBlocking);
        cudaEventCreateWithFlags(&evFork, cudaEventDisableTiming);
        cudaEventCreateWithFlags(&evJoin, cudaEventDisableTiming);
        attr_set = true;
    }

    // ---- fork: prep chain on sB, CSR chain on default stream ----
    cudaEventRecord(evFork, 0);
    cudaStreamWaitEvent(sB, evFork, 0);

    wconv_kernel<<<1024, 256, 0, sB>>>(Wbs, Wbn);
    prep_kernel<<<(int)((4LL * NN * 40 + 255) / 256), 256, 0, sB>>>(z, vert, vpot);
    l0_gemm_kernel<<<NN / 32, 256, 0, sB>>>(vert, vpot, W0s, W0n);
    cudaEventRecord(evJoin, sB);

    // default stream: CSR build (detect fused into zero_counts)
    zero_counts_kernel<<<(NN + 1023) / 1024, 1024>>>(edges);
    count_kernel<<<(EE + 255) / 256, 256>>>(edges);
    scan_block_kernel<<<SCAN_BLOCKS, 1024>>>();
    scan_tops_kernel<<<1, 128>>>();
    scan_add_kernel<<<SCAN_BLOCKS, 1024>>>();
    scatter_kernel<<<(EE + 255) / 256, 256>>>(edges);

    cudaStreamWaitEvent(0, evJoin, 0);

    // layer 0 combine -> A buffer 0
    combine_body_kernel<<<(NN * 32 + 255) / 256, 256>>>(b0, 0);

    // 4 body layers
    for (int i = 0; i < 4; i++) {
        tc_gemm_kernel<<<MTILES, 256, GEMM_SMEM>>>(i);
        if (i < 3)
            combine_body_kernel<<<(NN * 32 + 255) / 256, 256>>>(bb + i * HH, i + 1);
        else
            combine_head_kernel<<<(NN * 32 + 255) / 256, 256>>>(bb + 3 * HH, Wls, Wln);
    }

    // head
    final_combine_kernel<<<(NN + 255) / 256, 256>>>(bl, out);
}

// round 15
// speedup vs baseline: 1.1657x; 1.1197x over previous
#include <cuda_runtime.h>
#include <cuda_bf16.h>
#include <cuda_fp16.h>
#include <cstdint>

#define NN 100000
#define EE 600000
#define HH 128
#define ZZ 64
#define BIN 198
#define SCAN_BLOCKS ((NN + 1023) / 1024)   // 98
#define MTILES ((NN + 127) / 128)          // 782

// ---------------- device scratch (no allocations allowed) ----------------
__device__ int   g_i64;
__device__ int   g_counts[NN];
__device__ int   g_off[NN + 1];
__device__ int   g_cursor[NN];
__device__ int   g_csr[EE];
__device__ int   g_bsums[SCAN_BLOCKS];
__device__ int   g_bsum_ex[SCAN_BLOCKS];
__device__ float  g_ts[(size_t)NN * 128];              // GEMM out, s-half (fp32, streamed)
__device__ __half g_tn[(size_t)NN * 128];              // GEMM out, n-half (fp16; L2-hot, gathered)
__device__ float  g_q[(size_t)NN * 6];                 // head per-node outputs
__device__ __nv_bfloat16 g_Ahi[(size_t)4 * NN * 256];  // per-layer concat A, hi part
__device__ __nv_bfloat16 g_Alo[(size_t)4 * NN * 256];  // lo part
__device__ __nv_bfloat16 g_Whi[4 * 256 * 256];         // [layer][n(256)][k(256)]
__device__ __nv_bfloat16 g_Wlo[4 * 256 * 256];
__device__ float g_Wf[4 * 256 * 256];                  // fp32 [l][k][n] (fallback path)

// ---------------- arch feature gate ----------------
#if defined(__CUDA_ARCH_FEAT_SM103_ALL) || defined(__CUDA_ARCH_FEAT_SM100_ALL) || \
    defined(__CUDA_ARCH_FEAT_SM101_ALL) || defined(__CUDA_ARCH_FEAT_SM110_ALL)
#define TC_OK 1
#else
#define TC_OK 0
#endif

// ---------------- L2 policy-based cache hints ----------------
__device__ __forceinline__ uint64_t pol_evict_last() {
    uint64_t p;
    asm("createpolicy.fractional.L2::evict_last.b64 %0, 1.0;" : "=l"(p));
    return p;
}
__device__ __forceinline__ uint64_t pol_evict_first() {
    uint64_t p;
    asm("createpolicy.fractional.L2::evict_first.b64 %0, 1.0;" : "=l"(p));
    return p;
}
__device__ __forceinline__ float4 ldg_hint_f4(const float4* p, uint64_t pol) {
    float4 v;
    asm volatile("ld.global.nc.L2::cache_hint.v4.f32 {%0,%1,%2,%3}, [%4], %5;"
                 : "=f"(v.x), "=f"(v.y), "=f"(v.z), "=f"(v.w) : "l"(p), "l"(pol));
    return v;
}
__device__ __forceinline__ uint4 ldg_hint_u4(const void* p, uint64_t pol) {
    uint4 v;
    asm volatile("ld.global.nc.L2::cache_hint.v4.b32 {%0,%1,%2,%3}, [%4], %5;"
                 : "=r"(v.x), "=r"(v.y), "=r"(v.z), "=r"(v.w) : "l"(p), "l"(pol));
    return v;
}
__device__ __forceinline__ void stg_hint_u4(void* p, uint4 v, uint64_t pol) {
    asm volatile("st.global.L2::cache_hint.v4.b32 [%0], {%1,%2,%3,%4}, %5;"
                 :: "l"(p), "r"(v.x), "r"(v.y), "r"(v.z), "r"(v.w), "l"(pol) : "memory");
}
__device__ __forceinline__ void stg_hint_f(float* p, float v, uint64_t pol) {
    asm volatile("st.global.L2::cache_hint.f32 [%0], %1, %2;"
                 :: "l"(p), "f"(v), "l"(pol) : "memory");
}
// fp16 neighbor row load: 4 halves (8B) per lane, converted to float4
__device__ __forceinline__ float4 ldh_hint_f4(const __half* p, uint64_t pol) {
    uint32_t a, b;
    asm volatile("ld.global.nc.L2::cache_hint.v2.b32 {%0,%1}, [%2], %3;"
                 : "=r"(a), "=r"(b) : "l"(p), "l"(pol));
    __half2 h0 = *reinterpret_cast<__half2*>(&a);
    __half2 h1 = *reinterpret_cast<__half2*>(&b);
    float2 f0 = __half22float2(h0);
    float2 f1 = __half22float2(h1);
    return make_float4(f0.x, f0.y, f1.x, f1.y);
}
__device__ __forceinline__ uint32_t pack_h2(float lo, float hi) {
    __half2 h = __floats2half2_rn(lo, hi);     // x=lo (low half in memory), y=hi
    return *reinterpret_cast<uint32_t*>(&h);
}

// ---------------- PTX helpers ----------------
__device__ __forceinline__ uint32_t elect_one_pred() {
    uint32_t pred;
    asm volatile("{\n\t.reg .pred p;\n\telect.sync _|p, 0xFFFFFFFF;\n\tselp.b32 %0, 1, 0, p;\n\t}"
                 : "=r"(pred));
    return pred;
}
__device__ __forceinline__ uint32_t smem_to_u32(const void* p) {
    uint32_t a;
    asm("{ .reg .u64 t; cvta.to.shared.u64 t, %1; cvt.u32.u64 %0, t; }" : "=r"(a) : "l"(p));
    return a;
}
#define SMEM_SWIZZLE_128B(x) ((x) ^ (((x) >> 3) & 0x70))

#define TCGEN05_ALLOC(sa, n) \
    asm volatile("tcgen05.alloc.cta_group::1.sync.aligned.shared::cta.b32 [%0], %1;" \
                 :: "r"((uint32_t)(sa)), "r"((uint32_t)(n)) : "memory")
#define TCGEN05_DEALLOC(t, n) \
    asm volatile("tcgen05.dealloc.cta_group::1.sync.aligned.b32 %0, %1;" :: "r"(t), "r"(n))
#define TCGEN05_RELINQ() \
    asm volatile("tcgen05.relinquish_alloc_permit.cta_group::1.sync.aligned;")
#define TCGEN05_COMMIT(mb) \
    asm volatile("tcgen05.commit.cta_group::1.mbarrier::arrive::one.shared::cluster.b64 [%0];" \
                 :: "r"((uint32_t)(mb)) : "memory")
#define TCGEN05_FENCE_AFTER() asm volatile("tcgen05.fence::after_thread_sync;" ::: "memory")
#define TCGEN05_FENCE_BEFORE() asm volatile("tcgen05.fence::before_thread_sync;" ::: "memory")
#define TCGEN05_WAIT_LD() asm volatile("tcgen05.wait::ld.sync.aligned;" ::: "memory")
#define FENCE_ASYNC() asm volatile("fence.proxy.async.shared::cta;" ::: "memory")
#define MBARRIER_INIT(mb, c) \
    asm volatile("mbarrier.init.shared.b64 [%0], %1;" :: "r"((uint32_t)(mb)), "r"((uint32_t)(c)) : "memory")

#define MBARRIER_WAIT_PARITY(mb, ph) do { \
    uint32_t _m = (uint32_t)(mb), _p = (uint32_t)(ph), _d; \
    asm volatile("{\n\t.reg .pred p;\n\t" \
        "mbarrier.try_wait.parity.acquire.cta.shared::cta.b64 p, [%1], %2;\n\t" \
        "selp.b32 %0, 1, 0, p;\n\t}" : "=r"(_d) : "r"(_m), "r"(_p) : "memory"); \
    if (!_d) { \
        asm volatile("{\n\t.reg .pred P1;\n\t" \
            "WL_%=:\n\t" \
            "mbarrier.try_wait.parity.acquire.cta.shared::cta.b64 P1, [%0], %1, 0x989680;\n\t" \
            "@P1 bra.uni WD_%=;\n\tbra.uni WL_%=;\n\tWD_%=:\n\t}" \
            :: "r"(_m), "r"(_p) : "memory"); \
    } \
} while (0)

#define TCGEN05_LD_X32(r, ta) \
    asm volatile("tcgen05.ld.sync.aligned.32x32b.x32.b32 " \
        "{%0, %1, %2, %3, %4, %5, %6, %7, %8, %9, %10, %11, %12, %13, %14, %15, " \
        "%16, %17, %18, %19, %20, %21, %22, %23, %24, %25, %26, %27, %28, %29, %30, %31}, [%32];" \
        : "=r"((r)[0]), "=r"((r)[1]), "=r"((r)[2]), "=r"((r)[3]), "=r"((r)[4]), "=r"((r)[5]), \
          "=r"((r)[6]), "=r"((r)[7]), "=r"((r)[8]), "=r"((r)[9]), "=r"((r)[10]), "=r"((r)[11]), \
          "=r"((r)[12]), "=r"((r)[13]), "=r"((r)[14]), "=r"((r)[15]), "=r"((r)[16]), "=r"((r)[17]), \
          "=r"((r)[18]), "=r"((r)[19]), "=r"((r)[20]), "=r"((r)[21]), "=r"((r)[22]), "=r"((r)[23]), \
          "=r"((r)[24]), "=r"((r)[25]), "=r"((r)[26]), "=r"((r)[27]), "=r"((r)[28]), "=r"((r)[29]), \
          "=r"((r)[30]), "=r"((r)[31]) : "r"(ta))

#if TC_OK
__device__ __forceinline__ void mma_bf16_ss(uint32_t d, uint64_t a, uint64_t b,
                                            uint32_t idesc, bool en) {
    uint32_t e = en ? 1u : 0u;
    asm volatile(
        "{\n\t.reg .pred p;\n\tsetp.ne.u32 p, %5, 0;\n\t"
        "tcgen05.mma.cta_group::1.kind::f16 [%0], %1, %2, %3, {%4, %4, %4, %4}, p;\n\t}"
        :: "r"(d), "l"(a), "l"(b), "r"(idesc), "r"(0u), "r"(e) : "memory");
}
#endif

__device__ __forceinline__ uint64_t make_desc(uint32_t addr) {
    const uint64_t base = (2ull << 61) | (1ull << 46) | (64ull << 32) | (1ull << 16);
    return base | ((uint64_t)(addr >> 4) & 0x3FFF);
}

#define MMA_IDESC ((1u << 4) | (1u << 7) | (1u << 10) | ((128u / 8) << 17) | ((128u / 16) << 24))

__device__ __forceinline__ int2 edge_pair(const void* edges, int e) {
    if (g_i64) {
        longlong2 v = ((const longlong2*)edges)[e];
        return make_int2((int)v.x, (int)v.y);
    }
    return ((const int2*)edges)[e];
}
__device__ __forceinline__ void bf16_split(float x, __nv_bfloat16& h, __nv_bfloat16& l) {
    h = __float2bfloat16(x);
    l = __float2bfloat16(x - __bfloat162float(h));
}
__device__ __forceinline__ unsigned long long pack2(float x, float y) {
    unsigned long long d;
    asm("mov.b64 %0, {%1, %2};" : "=l"(d) : "f"(x), "f"(y));
    return d;
}
__device__ __forceinline__ unsigned long long fma2(unsigned long long a,
                                                   unsigned long long b,
                                                   unsigned long long c) {
    unsigned long long d;
    asm("fma.rn.f32x2 %0, %1, %2, %3;" : "=l"(d) : "l"(a), "l"(b), "l"(c));
    return d;
}

// ---------------- CSR construction ----------------
__global__ void zero_counts_kernel(const void* edges) {
    int i = blockIdx.x * blockDim.x + threadIdx.x;
    if (i < NN) g_counts[i] = 0;
    if (blockIdx.x == 0 && threadIdx.x < 32) {      // fused int64 detection
        const long long* p = (const long long*)edges;
        long long v = p[threadIdx.x];
        bool ok = (v >= 0 && v < NN);
        unsigned m = __ballot_sync(0xffffffff, ok);
        if (threadIdx.x == 0) g_i64 = (m == 0xffffffffu) ? 1 : 0;
    }
}
__global__ void count_kernel(const void* edges) {
    int e = blockIdx.x * blockDim.x + threadIdx.x;
    if (e < EE) atomicAdd(&g_counts[edge_pair(edges, e).y], 1);
}
__global__ void scan_block_kernel() {
    __shared__ int s[1024];
    int t = threadIdx.x;
    int i = blockIdx.x * 1024 + t;
    int v = (i < NN) ? g_counts[i] : 0;
    s[t] = v;
    __syncthreads();
#pragma unroll
    for (int d = 1; d < 1024; d <<= 1) {
        int x = (t >= d) ? s[t - d] : 0;
        __syncthreads();
        s[t] += x;
        __syncthreads();
    }
    if (i < NN) g_off[i] = s[t] - v;
    if (t == 1023) g_bsums[blockIdx.x] = s[1023];
}
__global__ void scan_tops_kernel() {
    __shared__ int s[128];
    int t = threadIdx.x;
    int v = (t < SCAN_BLOCKS) ? g_bsums[t] : 0;
    s[t] = v;
    __syncthreads();
#pragma unroll
    for (int d = 1; d < 128; d <<= 1) {
        int x = (t >= d) ? s[t - d] : 0;
        __syncthreads();
        s[t] += x;
        __syncthreads();
    }
    if (t < SCAN_BLOCKS) g_bsum_ex[t] = s[t] - v;
}
__global__ void scan_add_kernel() {
    int i = blockIdx.x * 1024 + threadIdx.x;
    if (i < NN) {
        int o = g_off[i] + g_bsum_ex[blockIdx.x];
        g_off[i] = o;
        g_cursor[i] = o;
    }
    if (i == 0) g_off[NN] = EE;
}
__global__ void scatter_kernel(const void* edges) {
    int e = blockIdx.x * blockDim.x + threadIdx.x;
    if (e < EE) {
        int2 p = edge_pair(edges, e);
        g_csr[atomicAdd(&g_cursor[p.y], 1)] = p.x;
    }
}

// ---------------- weight transpose+split ----------------
__global__ void wconv_kernel(const float* __restrict__ Wbs, const float* __restrict__ Wbn) {
    int idx = blockIdx.x * 256 + threadIdx.x;   // 4*256*256
    int l = idx >> 16, n = (idx >> 8) & 255, k = idx & 255;
    float v = 0.f;
    if (k < BIN)
        v = (n < 128) ? Wbs[(size_t)l * BIN * HH + k * 128 + n]
                      : Wbn[(size_t)l * BIN * HH + k * 128 + (n - 128)];
    __nv_bfloat16 h, lo;
    bf16_split(v, h, lo);
    g_Whi[idx] = h;
    g_Wlo[idx] = lo;
    g_Wf[(((size_t)l * 256) + k) * 256 + n] = v;
}

// ---------------- prep: fill z/in6/pad cols [128,208) of all 4 A buffers ---------
__global__ void __launch_bounds__(256)
prep_kernel(const float* __restrict__ z,
            const float* __restrict__ vert,
            const float* __restrict__ vpot) {
    long long idx = (long long)blockIdx.x * 256 + threadIdx.x;   // 4*NN*40
    if (idx >= 4LL * NN * 40) return;
    int t = (int)(idx % 40);
    long long r = idx / 40;
    int n = (int)(r % NN);
    int l = (int)(r / NN);
    int c = 128 + t * 2;
    float v0, v1;
    if (c < 192) {
        float2 zv = *(const float2*)(z + ((size_t)l * NN + n) * 64 + (c - 128));
        v0 = zv.x; v1 = zv.y;
    } else if (c < 198) {
        int j0 = c - 192, j1 = c - 191;
        v0 = (j0 < 3) ? vert[n * 3 + j0] : vpot[n * 3 + j0 - 3];
        v1 = (j1 < 3) ? vert[n * 3 + j1] : vpot[n * 3 + j1 - 3];
    } else {
        v0 = 0.f; v1 = 0.f;
    }
    __nv_bfloat16 h[2], lo[2];
    bf16_split(v0, h[0], lo[0]);
    bf16_split(v1, h[1], lo[1]);
    size_t base = ((size_t)l * NN + n) * 256 + c;
    *(uint32_t*)(g_Ahi + base) = *(const uint32_t*)h;
    *(uint32_t*)(g_Alo + base) = *(const uint32_t*)lo;
}

// ---------------- layer 0 GEMM: 32 nodes per block ----------------
__global__ void __launch_bounds__(256)
l0_gemm_kernel(const float* __restrict__ vert,
               const float* __restrict__ vpot,
               const float* __restrict__ W0s,
               const float* __restrict__ W0n) {
    __shared__ float xi[32][6];
    int t = threadIdx.x;
    int n0 = blockIdx.x * 32;
    if (t < 192) {
        int i = t / 6, k = t % 6;
        int n = n0 + i;
        xi[i][k] = (k < 3) ? vert[n * 3 + k] : vpot[n * 3 + (k - 3)];
    }
    __syncthreads();
    uint64_t pef = pol_evict_first();
    int c = t;
    const float* B = (c < 128) ? (W0s + c) : (W0n + (c - 128));
    float w0 = B[0], w1 = B[HH], w2 = B[2 * HH], w3 = B[3 * HH], w4 = B[4 * HH], w5 = B[5 * HH];
#pragma unroll 4
    for (int i = 0; i < 32; i++) {
        float acc = w0 * xi[i][0] + w1 * xi[i][1] + w2 * xi[i][2] +
                    w3 * xi[i][3] + w4 * xi[i][4] + w5 * xi[i][5];
        int n = n0 + i;
        if (c < 128) stg_hint_f(g_ts + (size_t)n * 128 + c, acc, pef);
        else         g_tn[(size_t)n * 128 + (c - 128)] = __float2half_rn(acc);
    }
}

// ---------------- combine (body): agg+bias+relu -> feat cols of buffer[layer] ----
__global__ void __launch_bounds__(256)
combine_body_kernel(const float* __restrict__ bias, int layer) {
    uint64_t pel = pol_evict_last();
    uint64_t pef = pol_evict_first();
    int gw = (blockIdx.x * blockDim.x + threadIdx.x) >> 5;
    int lane = threadIdx.x & 31;
    if (gw >= NN) return;
    int n = gw;
    int s0 = g_off[n], s1 = g_off[n + 1];
    float4 acc = make_float4(0.f, 0.f, 0.f, 0.f);
    int e = s0;
    for (; e + 4 <= s1; e += 4) {
        int i0 = g_csr[e], i1 = g_csr[e + 1], i2 = g_csr[e + 2], i3 = g_csr[e + 3];
        float4 v0 = ldh_hint_f4(g_tn + (size_t)i0 * 128 + lane * 4, pel);
        float4 v1 = ldh_hint_f4(g_tn + (size_t)i1 * 128 + lane * 4, pel);
        float4 v2 = ldh_hint_f4(g_tn + (size_t)i2 * 128 + lane * 4, pel);
        float4 v3 = ldh_hint_f4(g_tn + (size_t)i3 * 128 + lane * 4, pel);
        acc.x += (v0.x + v1.x) + (v2.x + v3.x);
        acc.y += (v0.y + v1.y) + (v2.y + v3.y);
        acc.z += (v0.z + v1.z) + (v2.z + v3.z);
        acc.w += (v0.w + v1.w) + (v2.w + v3.w);
    }
    for (; e < s1; e++) {
        int s = g_csr[e];
        float4 v = ldh_hint_f4(g_tn + (size_t)s * 128 + lane * 4, pel);
        acc.x += v.x; acc.y += v.y; acc.z += v.z; acc.w += v.w;
    }
    float inv = 1.0f / (float)max(s1 - s0, 1);
    float4 ts = ldg_hint_f4((const float4*)(g_ts + (size_t)n * 128) + lane, pef);
    float4 b4 = ((const float4*)bias)[lane];
    float o[4];
    o[0] = fmaxf(ts.x + acc.x * inv + b4.x, 0.f);
    o[1] = fmaxf(ts.y + acc.y * inv + b4.y, 0.f);
    o[2] = fmaxf(ts.z + acc.z * inv + b4.z, 0.f);
    o[3] = fmaxf(ts.w + acc.w * inv + b4.w, 0.f);
    __nv_bfloat16 h[4], l[4];
#pragma unroll
    for (int j = 0; j < 4; j++) bf16_split(o[j], h[j], l[j]);
    size_t base = ((size_t)layer * NN + n) * 256 + lane * 4;
    *(uint2*)(g_Ahi + base) = *(const uint2*)h;
    *(uint2*)(g_Alo + base) = *(const uint2*)l;
}

// ---------------- combine (head): agg+bias+relu + fused head GEMM -> g_q --------
__global__ void __launch_bounds__(256)
combine_head_kernel(const float* __restrict__ bias,
                    const float* __restrict__ Wls,
                    const float* __restrict__ Wln) {
    __shared__ float Bs[128][6];
    int tid = threadIdx.x;
    for (int i = tid; i < 128 * 6; i += 256) {
        int k = i / 6, c = i % 6;
        Bs[k][c] = (c < 3) ? Wls[k * 3 + c] : Wln[k * 3 + (c - 3)];
    }
    __syncthreads();
    uint64_t pel = pol_evict_last();
    uint64_t pef = pol_evict_first();
    int gw = (blockIdx.x * blockDim.x + tid) >> 5;
    int lane = tid & 31;
    if (gw >= NN) return;
    int n = gw;
    int s0 = g_off[n], s1 = g_off[n + 1];
    float4 acc = make_float4(0.f, 0.f, 0.f, 0.f);
    int e = s0;
    for (; e + 4 <= s1; e += 4) {
        int i0 = g_csr[e], i1 = g_csr[e + 1], i2 = g_csr[e + 2], i3 = g_csr[e + 3];
        float4 v0 = ldh_hint_f4(g_tn + (size_t)i0 * 128 + lane * 4, pel);
        float4 v1 = ldh_hint_f4(g_tn + (size_t)i1 * 128 + lane * 4, pel);
        float4 v2 = ldh_hint_f4(g_tn + (size_t)i2 * 128 + lane * 4, pel);
        float4 v3 = ldh_hint_f4(g_tn + (size_t)i3 * 128 + lane * 4, pel);
        acc.x += (v0.x + v1.x) + (v2.x + v3.x);
        acc.y += (v0.y + v1.y) + (v2.y + v3.y);
        acc.z += (v0.z + v1.z) + (v2.z + v3.z);
        acc.w += (v0.w + v1.w) + (v2.w + v3.w);
    }
    for (; e < s1; e++) {
        int s = g_csr[e];
        float4 v = ldh_hint_f4(g_tn + (size_t)s * 128 + lane * 4, pel);
        acc.x += v.x; acc.y += v.y; acc.z += v.z; acc.w += v.w;
    }
    float inv = 1.0f / (float)max(s1 - s0, 1);
    float4 ts = ldg_hint_f4((const float4*)(g_ts + (size_t)n * 128) + lane, pef);
    float4 b4 = ((const float4*)bias)[lane];
    float o0 = fmaxf(ts.x + acc.x * inv + b4.x, 0.f);
    float o1 = fmaxf(ts.y + acc.y * inv + b4.y, 0.f);
    float o2 = fmaxf(ts.z + acc.z * inv + b4.z, 0.f);
    float o3 = fmaxf(ts.w + acc.w * inv + b4.w, 0.f);
    float p[6];
#pragma unroll
    for (int j = 0; j < 6; j++)
        p[j] = o0 * Bs[lane * 4 + 0][j] + o1 * Bs[lane * 4 + 1][j] +
               o2 * Bs[lane * 4 + 2][j] + o3 * Bs[lane * 4 + 3][j];
#pragma unroll
    for (int off = 16; off > 0; off >>= 1) {
#pragma unroll
        for (int j = 0; j < 6; j++)
            p[j] += __shfl_xor_sync(0xffffffff, p[j], off);
    }
    if (lane == 0) {
#pragma unroll
        for (int j = 0; j < 6; j++)
            g_q[(size_t)n * 6 + j] = p[j];
    }
}

// ---------------- body GEMM: tcgen05 (K=208 trimmed), SIMT fallback ----------
#define ST_BYTES 98304
#define SMEM_TILES 1024
#define GEMM_SMEM (SMEM_TILES + 2 * ST_BYTES)   // 197632

__global__ void __launch_bounds__(256, 1)
tc_gemm_kernel(int layer) {
#if TC_OK
    extern __shared__ char smem[];
    uint32_t sb = smem_to_u32(smem);
    int tid = threadIdx.x;
    int wid = tid >> 5;
    int row0 = blockIdx.x * 128;
    uint64_t pel = pol_evict_last();
    uint64_t pef = pol_evict_first();

    if (wid == 0) {
        TCGEN05_ALLOC(sb, 256);
        TCGEN05_RELINQ();
    }
    if (tid == 0) {
        MBARRIER_INIT(sb + 8, 1);
        MBARRIER_INIT(sb + 16, 1);
    }
    __syncthreads();
    uint32_t tmem;
    asm volatile("ld.shared.b32 %0, [%1];" : "=r"(tmem) : "r"(sb));

    const __nv_bfloat16* Ah_g = g_Ahi + (size_t)layer * NN * 256;
    const __nv_bfloat16* Al_g = g_Alo + (size_t)layer * NN * 256;
    const __nv_bfloat16* Wh = g_Whi + (size_t)layer * 65536;
    const __nv_bfloat16* Wl = g_Wlo + (size_t)layer * 65536;

    auto load_stage = [&](int kc, int st, bool full) {
        char* base = smem + SMEM_TILES + st * ST_BYTES;
        int c0 = kc * 64;
        if (full) {
#pragma unroll
            for (int i = 0; i < 4; i++) {           // A (stream once)
                int u = tid + i * 256;
                int m = u >> 3, j = u & 7;
                int n = row0 + m;
                uint4 vh = make_uint4(0u, 0u, 0u, 0u), vl = vh;
                if (n < NN) {
                    vh = ldg_hint_u4(Ah_g + (size_t)n * 256 + c0 + j * 8, pef);
                    vl = ldg_hint_u4(Al_g + (size_t)n * 256 + c0 + j * 8, pef);
                }
                uint32_t off = SMEM_SWIZZLE_128B((uint32_t)(m * 128 + j * 16));
                *(uint4*)(base + off) = vh;
                *(uint4*)(base + 16384 + off) = vl;
            }
#pragma unroll
            for (int i = 0; i < 8; i++) {           // B (hot, reused by all CTAs)
                int u = tid + i * 256;
                int r = u >> 3, j = u & 7;
                uint4 vh = ldg_hint_u4(Wh + (size_t)r * 256 + c0 + j * 8, pel);
                uint4 vl = ldg_hint_u4(Wl + (size_t)r * 256 + c0 + j * 8, pel);
                uint32_t off = SMEM_SWIZZLE_128B((uint32_t)(r * 128 + j * 16));
                *(uint4*)(base + 32768 + off) = vh;
                *(uint4*)(base + 65536 + off) = vl;
            }
        } else {
            {
                int m = tid >> 1, j = tid & 1;
                int n = row0 + m;
                uint4 vh = make_uint4(0u, 0u, 0u, 0u), vl = vh;
                if (n < NN) {
                    vh = ldg_hint_u4(Ah_g + (size_t)n * 256 + c0 + j * 8, pef);
                    vl = ldg_hint_u4(Al_g + (size_t)n * 256 + c0 + j * 8, pef);
                }
                uint32_t off = SMEM_SWIZZLE_128B((uint32_t)(m * 128 + j * 16));
                *(uint4*)(base + off) = vh;
                *(uint4*)(base + 16384 + off) = vl;
            }
#pragma unroll
            for (int i = 0; i < 2; i++) {
                int u = tid + i * 256;
                int r = u >> 1, j = u & 1;
                uint4 vh = ldg_hint_u4(Wh + (size_t)r * 256 + c0 + j * 8, pel);
                uint4 vl = ldg_hint_u4(Wl + (size_t)r * 256 + c0 + j * 8, pel);
                uint32_t off = SMEM_SWIZZLE_128B((uint32_t)(r * 128 + j * 16));
                *(uint4*)(base + 32768 + off) = vh;
                *(uint4*)(base + 65536 + off) = vl;
            }
        }
    };

    load_stage(0, 0, true);
    FENCE_ASYNC();
    __syncthreads();

    for (int c = 0; c < 4; c++) {
        int st = c & 1;
        int nk = (c < 3) ? 4 : 1;
        if (wid == 0 && elect_one_pred()) {
            uint32_t tb = sb + SMEM_TILES + st * ST_BYTES;
            uint64_t ah = make_desc(tb);
            uint64_t al = make_desc(tb + 16384);
            uint64_t bh = make_desc(tb + 32768);
            uint64_t bl = make_desc(tb + 65536);
            for (int k = 0; k < nk; k++) {
                bool en = !(c == 0 && k == 0);
                mma_bf16_ss(tmem,       ah + k * 2, bh + k * 2,        MMA_IDESC, en);
                mma_bf16_ss(tmem,       ah + k * 2, bl + k * 2,        MMA_IDESC, true);
                mma_bf16_ss(tmem,       al + k * 2, bh + k * 2,        MMA_IDESC, true);
                mma_bf16_ss(tmem + 128, ah + k * 2, bh + 1024 + k * 2, MMA_IDESC, en);
                mma_bf16_ss(tmem + 128, ah + k * 2, bl + 1024 + k * 2, MMA_IDESC, true);
                mma_bf16_ss(tmem + 128, al + k * 2, bh + 1024 + k * 2, MMA_IDESC, true);
            }
            TCGEN05_COMMIT(sb + 8 + 8 * st);
        }
        if (c < 3) {
            if (c >= 1) MBARRIER_WAIT_PARITY(sb + 8 + 8 * ((c + 1) & 1), 0);
            load_stage(c + 1, st ^ 1, (c + 1) < 3);
            FENCE_ASYNC();
        }
        __syncthreads();
    }

    MBARRIER_WAIT_PARITY(sb + 8, 1);
    MBARRIER_WAIT_PARITY(sb + 16, 1);
    TCGEN05_FENCE_AFTER();

    if (wid < 4) {
        int lane = tid & 31;
        int n = row0 + wid * 32 + lane;
#pragma unroll
        for (int cb = 0; cb < 256; cb += 32) {
            uint32_t r[32];
            TCGEN05_LD_X32(r, tmem + cb);
            TCGEN05_WAIT_LD();
            if (n < NN) {
                if (cb < 128) {
                    float* dst = g_ts + (size_t)n * 128 + cb;
#pragma unroll
                    for (int j = 0; j < 32; j += 4)
                        stg_hint_u4(dst + j, make_uint4(r[j], r[j + 1], r[j + 2], r[j + 3]), pef);
                } else {
                    // pack 32 fp32 cols -> 16 half2 words -> 4x uint4 stores
                    __half* dst = g_tn + (size_t)n * 128 + (cb - 128);
                    uint32_t hp[16];
#pragma unroll
                    for (int j = 0; j < 16; j++)
                        hp[j] = pack_h2(__uint_as_float(r[2 * j]),
                                        __uint_as_float(r[2 * j + 1]));
#pragma unroll
                    for (int j = 0; j < 4; j++)
                        stg_hint_u4(dst + j * 8,
                                    make_uint4(hp[4 * j], hp[4 * j + 1],
                                               hp[4 * j + 2], hp[4 * j + 3]), pel);
                }
            }
        }
        TCGEN05_FENCE_BEFORE();
    }
    __syncthreads();
    if (wid == 0) TCGEN05_DEALLOC(tmem, 256);
#else
    // ------- SIMT f32x2 fallback -------
    extern __shared__ char smem[];
    float (*As)[16][132] = reinterpret_cast<float(*)[16][132]>(smem);
    float (*Bs)[16][128] = reinterpret_cast<float(*)[16][128]>(smem + 2 * 16 * 132 * 4);

    const int tid = threadIdx.x;
    const int tx = tid & 15;
    const int ty = tid >> 4;
    const int row0 = blockIdx.x * 128;
    const float* Wf = g_Wf + (size_t)layer * 65536;
    const __nv_bfloat16* Ah_g = g_Ahi + (size_t)layer * NN * 256;
    const __nv_bfloat16* Al_g = g_Alo + (size_t)layer * NN * 256;

    for (int half = 0; half < 2; half++) {
        const int col0 = half * 128;
        unsigned long long acc[8][4];
#pragma unroll
        for (int i = 0; i < 8; i++)
#pragma unroll
            for (int j = 0; j < 4; j++) acc[i][j] = 0ull;

        float ra[8], rb[8];
        auto loadA = [&](int kt, float* r) {
            int kbase = kt * 16;
#pragma unroll
            for (int j = 0; j < 8; j++) {
                int l = tid + j * 256;
                int m = l >> 4, kk = l & 15;
                int n = row0 + m;
                int k = kbase + kk;
                float v = 0.f;
                if (n < NN)
                    v = __bfloat162float(Ah_g[(size_t)n * 256 + k]) +
                        __bfloat162float(Al_g[(size_t)n * 256 + k]);
                r[j] = v;
            }
        };
        auto loadB = [&](int kt, float* r) {
            int kbase = kt * 16;
#pragma unroll
            for (int j = 0; j < 8; j++) {
                int l = tid + j * 256;
                int c = l & 127;
                int k = kbase + (l >> 7);
                r[j] = Wf[(size_t)k * 256 + col0 + c];
            }
        };
        auto storeA = [&](int st, const float* r) {
#pragma unroll
            for (int j = 0; j < 8; j++) {
                int l = tid + j * 256;
                As[st][l & 15][l >> 4] = r[j];
            }
        };
        auto storeB = [&](int st, const float* r) {
#pragma unroll
            for (int j = 0; j < 8; j++) {
                int l = tid + j * 256;
                Bs[st][l >> 7][l & 127] = r[j];
            }
        };

        loadA(0, ra); loadB(0, rb);
        storeA(0, ra); storeB(0, rb);
        __syncthreads();

        for (int kt = 0; kt < 13; kt++) {
            int cur = kt & 1;
            if (kt < 12) { loadA(kt + 1, ra); loadB(kt + 1, rb); }
#pragma unroll
            for (int kk = 0; kk < 16; kk++) {
                float4 a0 = *(const float4*)&As[cur][kk][ty * 8];
                float4 a1 = *(const float4*)&As[cur][kk][ty * 8 + 4];
                ulonglong2 b0 = *(const ulonglong2*)&Bs[cur][kk][tx * 4];
                ulonglong2 b1 = *(const ulonglong2*)&Bs[cur][kk][64 + tx * 4];
                unsigned long long ad[8];
                ad[0] = pack2(a0.x, a0.x); ad[1] = pack2(a0.y, a0.y);
                ad[2] = pack2(a0.z, a0.z); ad[3] = pack2(a0.w, a0.w);
                ad[4] = pack2(a1.x, a1.x); ad[5] = pack2(a1.y, a1.y);
                ad[6] = pack2(a1.z, a1.z); ad[7] = pack2(a1.w, a1.w);
#pragma unroll
                for (int i = 0; i < 8; i++) {
                    acc[i][0] = fma2(ad[i], b0.x, acc[i][0]);
                    acc[i][1] = fma2(ad[i], b0.y, acc[i][1]);
                    acc[i][2] = fma2(ad[i], b1.x, acc[i][2]);
                    acc[i][3] = fma2(ad[i], b1.y, acc[i][3]);
                }
            }
            if (kt < 12) { storeA(cur ^ 1, ra); storeB(cur ^ 1, rb); }
            __syncthreads();
        }

#pragma unroll
        for (int i = 0; i < 8; i++) {
            int n = row0 + ty * 8 + i;
            if (n < NN) {
                float vals[8];
                *(ulonglong2*)&vals[0] = *(ulonglong2*)&acc[i][0];
                *(ulonglong2*)&vals[4] = *(ulonglong2*)&acc[i][2];
                if (half == 0) {
                    float* base = g_ts + (size_t)n * 128;
#pragma unroll
                    for (int j = 0; j < 4; j++) base[tx * 4 + j] = vals[j];
#pragma unroll
                    for (int j = 0; j < 4; j++) base[64 + tx * 4 + j] = vals[4 + j];
                } else {
                    __half* base = g_tn + (size_t)n * 128;
#pragma unroll
                    for (int j = 0; j < 4; j++) base[tx * 4 + j] = __float2half_rn(vals[j]);
#pragma unroll
                    for (int j = 0; j < 4; j++) base[64 + tx * 4 + j] = __float2half_rn(vals[4 + j]);
                }
            }
        }
        __syncthreads();
    }
#endif
}

// ---------------- final combine: out = q_s + agg(q_n)/deg + bl ----------------
__global__ void final_combine_kernel(const float* __restrict__ bl,
                                     float* __restrict__ out) {
    int n = blockIdx.x * blockDim.x + threadIdx.x;
    if (n >= NN) return;
    int s0 = g_off[n], s1 = g_off[n + 1];
    float a0 = 0.f, a1 = 0.f, a2 = 0.f;
    for (int e = s0; e < s1; e++) {
        int s = g_csr[e];
        a0 += g_q[(size_t)s * 6 + 3];
        a1 += g_q[(size_t)s * 6 + 4];
        a2 += g_q[(size_t)s * 6 + 5];
    }
    float inv = 1.0f / (float)max(s1 - s0, 1);
    out[n * 3 + 0] = g_q[(size_t)n * 6 + 0] + a0 * inv + bl[0];
    out[n * 3 + 1] = g_q[(size_t)n * 6 + 1] + a1 * inv + bl[1];
    out[n * 3 + 2] = g_q[(size_t)n * 6 + 2] + a2 * inv + bl[2];
}

// ---------------- launch ----------------
extern "C" void kernel_launch(void* const* d_in, const int* in_sizes, int n_in,
                              void* d_out, int out_size) {
    const float* vert = (const float*)d_in[0];
    const void*  edges = d_in[1];
    const float* vpot = (const float*)d_in[2];
    const float* z    = (const float*)d_in[3];
    const float* W0s  = (const float*)d_in[4];
    const float* W0n  = (const float*)d_in[5];
    const float* b0   = (const float*)d_in[6];
    const float* Wbs  = (const float*)d_in[7];
    const float* Wbn  = (const float*)d_in[8];
    const float* bb   = (const float*)d_in[9];
    const float* Wls  = (const float*)d_in[10];
    const float* Wln  = (const float*)d_in[11];
    const float* bl   = (const float*)d_in[12];
    float* out = (float*)d_out;

    static cudaStream_t sB = nullptr;
    static cudaEvent_t evFork = nullptr, evJoin = nullptr;
    static bool attr_set = false;
    if (!attr_set) {
        cudaFuncSetAttribute(tc_gemm_kernel, cudaFuncAttributeMaxDynamicSharedMemorySize, GEMM_SMEM);
        cudaStreamCreateWithFlags(&sB, cudaStreamNonBlocking);
        cudaEventCreateWithFlags(&evFork, cudaEventDisableTiming);
        cudaEventCreateWithFlags(&evJoin, cudaEventDisableTiming);
        attr_set = true;
    }

    // ---- fork: prep chain on sB, CSR chain on default stream ----
    cudaEventRecord(evFork, 0);
    cudaStreamWaitEvent(sB, evFork, 0);

    wconv_kernel<<<1024, 256, 0, sB>>>(Wbs, Wbn);
    prep_kernel<<<(int)((4LL * NN * 40 + 255) / 256), 256, 0, sB>>>(z, vert, vpot);
    l0_gemm_kernel<<<NN / 32, 256, 0, sB>>>(vert, vpot, W0s, W0n);
    cudaEventRecord(evJoin, sB);

    // default stream: CSR build (detect fused into zero_counts)
    zero_counts_kernel<<<(NN + 1023) / 1024, 1024>>>(edges);
    count_kernel<<<(EE + 255) / 256, 256>>>(edges);
    scan_block_kernel<<<SCAN_BLOCKS, 1024>>>();
    scan_tops_kernel<<<1, 128>>>();
    scan_add_kernel<<<SCAN_BLOCKS, 1024>>>();
    scatter_kernel<<<(EE + 255) / 256, 256>>>(edges);

    cudaStreamWaitEvent(0, evJoin, 0);

    // layer 0 combine -> A buffer 0
    combine_body_kernel<<<(NN * 32 + 255) / 256, 256>>>(b0, 0);

    // 4 body layers
    for (int i = 0; i < 4; i++) {
        tc_gemm_kernel<<<MTILES, 256, GEMM_SMEM>>>(i);
        if (i < 3)
            combine_body_kernel<<<(NN * 32 + 255) / 256, 256>>>(bb + i * HH, i + 1);
        else
            combine_head_kernel<<<(NN * 32 + 255) / 256, 256>>>(bb + 3 * HH, Wls, Wln);
    }

    // head
    final_combine_kernel<<<(NN + 255) / 256, 256>>>(bl, out);
}

// round 16
// speedup vs baseline: 1.3832x; 1.1866x over previous
#include <cuda_runtime.h>
#include <cuda_bf16.h>
#include <cuda_fp16.h>
#include <cstdint>

#define NN 100000
#define EE 600000
#define HH 128
#define ZZ 64
#define BIN 198
#define SCAN_BLOCKS ((NN + 1023) / 1024)   // 98
#define MTILES ((NN + 127) / 128)          // 782

// ---------------- device scratch (no allocations allowed) ----------------
__device__ int    g_i64;
__device__ int    g_counts[NN];
__device__ int    g_off[NN + 1];
__device__ int    g_cursor[NN];
__device__ int    g_csr[EE];
__device__ int    g_bsums[SCAN_BLOCKS];
__device__ int    g_bsum_ex[SCAN_BLOCKS];
__device__ __half g_ts[(size_t)NN * 128];              // GEMM out, s-half (fp16, streamed)
__device__ __half g_tn[(size_t)NN * 128];              // GEMM out, n-half (fp16; L2-hot)
__device__ float  g_q[(size_t)NN * 6];                 // head per-node outputs
__device__ __half g_Af[(size_t)4 * NN * 256];          // per-layer concat A (fp16, single)
__device__ __half g_Wh[4 * 256 * 256];                 // weights fp16 hi [layer][n][k]
__device__ __half g_Wl[4 * 256 * 256];                 // weights fp16 lo (residual)
__device__ float  g_Wf[4 * 256 * 256];                 // fp32 [l][k][n] (fallback path)

// ---------------- arch feature gate ----------------
#if defined(__CUDA_ARCH_FEAT_SM103_ALL) || defined(__CUDA_ARCH_FEAT_SM100_ALL) || \
    defined(__CUDA_ARCH_FEAT_SM101_ALL) || defined(__CUDA_ARCH_FEAT_SM110_ALL)
#define TC_OK 1
#else
#define TC_OK 0
#endif

// ---------------- L2 policy-based cache hints ----------------
__device__ __forceinline__ uint64_t pol_evict_last() {
    uint64_t p;
    asm("createpolicy.fractional.L2::evict_last.b64 %0, 1.0;" : "=l"(p));
    return p;
}
__device__ __forceinline__ uint64_t pol_evict_first() {
    uint64_t p;
    asm("createpolicy.fractional.L2::evict_first.b64 %0, 1.0;" : "=l"(p));
    return p;
}
__device__ __forceinline__ uint4 ldg_hint_u4(const void* p, uint64_t pol) {
    uint4 v;
    asm volatile("ld.global.nc.L2::cache_hint.v4.b32 {%0,%1,%2,%3}, [%4], %5;"
                 : "=r"(v.x), "=r"(v.y), "=r"(v.z), "=r"(v.w) : "l"(p), "l"(pol));
    return v;
}
__device__ __forceinline__ void stg_hint_u4(void* p, uint4 v, uint64_t pol) {
    asm volatile("st.global.L2::cache_hint.v4.b32 [%0], {%1,%2,%3,%4}, %5;"
                 :: "l"(p), "r"(v.x), "r"(v.y), "r"(v.z), "r"(v.w), "l"(pol) : "memory");
}
// fp16 row load: 4 halves (8B) per lane, converted to float4
__device__ __forceinline__ float4 ldh_hint_f4(const __half* p, uint64_t pol) {
    uint32_t a, b;
    asm volatile("ld.global.nc.L2::cache_hint.v2.b32 {%0,%1}, [%2], %3;"
                 : "=r"(a), "=r"(b) : "l"(p), "l"(pol));
    __half2 h0 = *reinterpret_cast<__half2*>(&a);
    __half2 h1 = *reinterpret_cast<__half2*>(&b);
    float2 f0 = __half22float2(h0);
    float2 f1 = __half22float2(h1);
    return make_float4(f0.x, f0.y, f1.x, f1.y);
}
__device__ __forceinline__ uint32_t pack_h2(float lo, float hi) {
    __half2 h = __floats2half2_rn(lo, hi);
    return *reinterpret_cast<uint32_t*>(&h);
}
__device__ __forceinline__ void stg_hint_u2(void* p, uint32_t a, uint32_t b, uint64_t pol) {
    asm volatile("st.global.L2::cache_hint.v2.b32 [%0], {%1,%2}, %3;"
                 :: "l"(p), "r"(a), "r"(b), "l"(pol) : "memory");
}

// ---------------- PTX helpers ----------------
__device__ __forceinline__ uint32_t elect_one_pred() {
    uint32_t pred;
    asm volatile("{\n\t.reg .pred p;\n\telect.sync _|p, 0xFFFFFFFF;\n\tselp.b32 %0, 1, 0, p;\n\t}"
                 : "=r"(pred));
    return pred;
}
__device__ __forceinline__ uint32_t smem_to_u32(const void* p) {
    uint32_t a;
    asm("{ .reg .u64 t; cvta.to.shared.u64 t, %1; cvt.u32.u64 %0, t; }" : "=r"(a) : "l"(p));
    return a;
}
#define SMEM_SWIZZLE_128B(x) ((x) ^ (((x) >> 3) & 0x70))

#define TCGEN05_ALLOC(sa, n) \
    asm volatile("tcgen05.alloc.cta_group::1.sync.aligned.shared::cta.b32 [%0], %1;" \
                 :: "r"((uint32_t)(sa)), "r"((uint32_t)(n)) : "memory")
#define TCGEN05_DEALLOC(t, n) \
    asm volatile("tcgen05.dealloc.cta_group::1.sync.aligned.b32 %0, %1;" :: "r"(t), "r"(n))
#define TCGEN05_RELINQ() \
    asm volatile("tcgen05.relinquish_alloc_permit.cta_group::1.sync.aligned;")
#define TCGEN05_COMMIT(mb) \
    asm volatile("tcgen05.commit.cta_group::1.mbarrier::arrive::one.shared::cluster.b64 [%0];" \
                 :: "r"((uint32_t)(mb)) : "memory")
#define TCGEN05_FENCE_AFTER() asm volatile("tcgen05.fence::after_thread_sync;" ::: "memory")
#define TCGEN05_FENCE_BEFORE() asm volatile("tcgen05.fence::before_thread_sync;" ::: "memory")
#define TCGEN05_WAIT_LD() asm volatile("tcgen05.wait::ld.sync.aligned;" ::: "memory")
#define FENCE_ASYNC() asm volatile("fence.proxy.async.shared::cta;" ::: "memory")
#define MBARRIER_INIT(mb, c) \
    asm volatile("mbarrier.init.shared.b64 [%0], %1;" :: "r"((uint32_t)(mb)), "r"((uint32_t)(c)) : "memory")

#define MBARRIER_WAIT_PARITY(mb, ph) do { \
    uint32_t _m = (uint32_t)(mb), _p = (uint32_t)(ph), _d; \
    asm volatile("{\n\t.reg .pred p;\n\t" \
        "mbarrier.try_wait.parity.acquire.cta.shared::cta.b64 p, [%1], %2;\n\t" \
        "selp.b32 %0, 1, 0, p;\n\t}" : "=r"(_d) : "r"(_m), "r"(_p) : "memory"); \
    if (!_d) { \
        asm volatile("{\n\t.reg .pred P1;\n\t" \
            "WL_%=:\n\t" \
            "mbarrier.try_wait.parity.acquire.cta.shared::cta.b64 P1, [%0], %1, 0x989680;\n\t" \
            "@P1 bra.uni WD_%=;\n\tbra.uni WL_%=;\n\tWD_%=:\n\t}" \
            :: "r"(_m), "r"(_p) : "memory"); \
    } \
} while (0)

#define TCGEN05_LD_X32(r, ta) \
    asm volatile("tcgen05.ld.sync.aligned.32x32b.x32.b32 " \
        "{%0, %1, %2, %3, %4, %5, %6, %7, %8, %9, %10, %11, %12, %13, %14, %15, " \
        "%16, %17, %18, %19, %20, %21, %22, %23, %24, %25, %26, %27, %28, %29, %30, %31}, [%32];" \
        : "=r"((r)[0]), "=r"((r)[1]), "=r"((r)[2]), "=r"((r)[3]), "=r"((r)[4]), "=r"((r)[5]), \
          "=r"((r)[6]), "=r"((r)[7]), "=r"((r)[8]), "=r"((r)[9]), "=r"((r)[10]), "=r"((r)[11]), \
          "=r"((r)[12]), "=r"((r)[13]), "=r"((r)[14]), "=r"((r)[15]), "=r"((r)[16]), "=r"((r)[17]), \
          "=r"((r)[18]), "=r"((r)[19]), "=r"((r)[20]), "=r"((r)[21]), "=r"((r)[22]), "=r"((r)[23]), \
          "=r"((r)[24]), "=r"((r)[25]), "=r"((r)[26]), "=r"((r)[27]), "=r"((r)[28]), "=r"((r)[29]), \
          "=r"((r)[30]), "=r"((r)[31]) : "r"(ta))

#if TC_OK
__device__ __forceinline__ void mma_f16_ss(uint32_t d, uint64_t a, uint64_t b,
                                           uint32_t idesc, bool en) {
    uint32_t e = en ? 1u : 0u;
    asm volatile(
        "{\n\t.reg .pred p;\n\tsetp.ne.u32 p, %5, 0;\n\t"
        "tcgen05.mma.cta_group::1.kind::f16 [%0], %1, %2, %3, {%4, %4, %4, %4}, p;\n\t}"
        :: "r"(d), "l"(a), "l"(b), "r"(idesc), "r"(0u), "r"(e) : "memory");
}
#endif

__device__ __forceinline__ uint64_t make_desc(uint32_t addr) {
    const uint64_t base = (2ull << 61) | (1ull << 46) | (64ull << 32) | (1ull << 16);
    return base | ((uint64_t)(addr >> 4) & 0x3FFF);
}

// idesc: F32 accum, F16 a/b (atype=btype=0), N=128, M=128
#define MMA_IDESC ((1u << 4) | ((128u / 8) << 17) | ((128u / 16) << 24))

__device__ __forceinline__ int2 edge_pair(const void* edges, int e) {
    if (g_i64) {
        longlong2 v = ((const longlong2*)edges)[e];
        return make_int2((int)v.x, (int)v.y);
    }
    return ((const int2*)edges)[e];
}
__device__ __forceinline__ void fp16_split(float x, __half& h, __half& l) {
    h = __float2half_rn(x);
    l = __float2half_rn(x - __half2float(h));
}
__device__ __forceinline__ unsigned long long pack2(float x, float y) {
    unsigned long long d;
    asm("mov.b64 %0, {%1, %2};" : "=l"(d) : "f"(x), "f"(y));
    return d;
}
__device__ __forceinline__ unsigned long long fma2(unsigned long long a,
                                                   unsigned long long b,
                                                   unsigned long long c) {
    unsigned long long d;
    asm("fma.rn.f32x2 %0, %1, %2, %3;" : "=l"(d) : "l"(a), "l"(b), "l"(c));
    return d;
}

// ---------------- CSR construction ----------------
__global__ void zero_counts_kernel(const void* edges) {
    int i = blockIdx.x * blockDim.x + threadIdx.x;
    if (i < NN) g_counts[i] = 0;
    if (blockIdx.x == 0 && threadIdx.x < 32) {
        const long long* p = (const long long*)edges;
        long long v = p[threadIdx.x];
        bool ok = (v >= 0 && v < NN);
        unsigned m = __ballot_sync(0xffffffff, ok);
        if (threadIdx.x == 0) g_i64 = (m == 0xffffffffu) ? 1 : 0;
    }
}
__global__ void count_kernel(const void* edges) {
    int e = blockIdx.x * blockDim.x + threadIdx.x;
    if (e < EE) atomicAdd(&g_counts[edge_pair(edges, e).y], 1);
}
__global__ void scan_block_kernel() {
    __shared__ int s[1024];
    int t = threadIdx.x;
    int i = blockIdx.x * 1024 + t;
    int v = (i < NN) ? g_counts[i] : 0;
    s[t] = v;
    __syncthreads();
#pragma unroll
    for (int d = 1; d < 1024; d <<= 1) {
        int x = (t >= d) ? s[t - d] : 0;
        __syncthreads();
        s[t] += x;
        __syncthreads();
    }
    if (i < NN) g_off[i] = s[t] - v;
    if (t == 1023) g_bsums[blockIdx.x] = s[1023];
}
__global__ void scan_tops_kernel() {
    __shared__ int s[128];
    int t = threadIdx.x;
    int v = (t < SCAN_BLOCKS) ? g_bsums[t] : 0;
    s[t] = v;
    __syncthreads();
#pragma unroll
    for (int d = 1; d < 128; d <<= 1) {
        int x = (t >= d) ? s[t - d] : 0;
        __syncthreads();
        s[t] += x;
        __syncthreads();
    }
    if (t < SCAN_BLOCKS) g_bsum_ex[t] = s[t] - v;
}
__global__ void scan_add_kernel() {
    int i = blockIdx.x * 1024 + threadIdx.x;
    if (i < NN) {
        int o = g_off[i] + g_bsum_ex[blockIdx.x];
        g_off[i] = o;
        g_cursor[i] = o;
    }
    if (i == 0) g_off[NN] = EE;
}
__global__ void scatter_kernel(const void* edges) {
    int e = blockIdx.x * blockDim.x + threadIdx.x;
    if (e < EE) {
        int2 p = edge_pair(edges, e);
        g_csr[atomicAdd(&g_cursor[p.y], 1)] = p.x;
    }
}

// ---------------- weight transpose + fp16 hi/lo split ----------------
__global__ void wconv_kernel(const float* __restrict__ Wbs, const float* __restrict__ Wbn) {
    int idx = blockIdx.x * 256 + threadIdx.x;   // 4*256*256
    int l = idx >> 16, n = (idx >> 8) & 255, k = idx & 255;
    float v = 0.f;
    if (k < BIN)
        v = (n < 128) ? Wbs[(size_t)l * BIN * HH + k * 128 + n]
                      : Wbn[(size_t)l * BIN * HH + k * 128 + (n - 128)];
    __half h, lo;
    fp16_split(v, h, lo);
    g_Wh[idx] = h;
    g_Wl[idx] = lo;
    g_Wf[(((size_t)l * 256) + k) * 256 + n] = v;
}

// ---------------- prep: fill z/in6/pad cols [128,208) of all 4 A buffers ---------
__global__ void __launch_bounds__(256)
prep_kernel(const float* __restrict__ z,
            const float* __restrict__ vert,
            const float* __restrict__ vpot) {
    long long idx = (long long)blockIdx.x * 256 + threadIdx.x;   // 4*NN*40
    if (idx >= 4LL * NN * 40) return;
    int t = (int)(idx % 40);
    long long r = idx / 40;
    int n = (int)(r % NN);
    int l = (int)(r / NN);
    int c = 128 + t * 2;
    float v0, v1;
    if (c < 192) {
        float2 zv = *(const float2*)(z + ((size_t)l * NN + n) * 64 + (c - 128));
        v0 = zv.x; v1 = zv.y;
    } else if (c < 198) {
        int j0 = c - 192, j1 = c - 191;
        v0 = (j0 < 3) ? vert[n * 3 + j0] : vpot[n * 3 + j0 - 3];
        v1 = (j1 < 3) ? vert[n * 3 + j1] : vpot[n * 3 + j1 - 3];
    } else {
        v0 = 0.f; v1 = 0.f;
    }
    size_t base = ((size_t)l * NN + n) * 256 + c;
    *(uint32_t*)(g_Af + base) = pack_h2(v0, v1);
}

// ---------------- layer 0 GEMM: 32 nodes per block ----------------
__global__ void __launch_bounds__(256)
l0_gemm_kernel(const float* __restrict__ vert,
               const float* __restrict__ vpot,
               const float* __restrict__ W0s,
               const float* __restrict__ W0n) {
    __shared__ float xi[32][6];
    int t = threadIdx.x;
    int n0 = blockIdx.x * 32;
    if (t < 192) {
        int i = t / 6, k = t % 6;
        int n = n0 + i;
        xi[i][k] = (k < 3) ? vert[n * 3 + k] : vpot[n * 3 + (k - 3)];
    }
    __syncthreads();
    int c = t;
    const float* B = (c < 128) ? (W0s + c) : (W0n + (c - 128));
    float w0 = B[0], w1 = B[HH], w2 = B[2 * HH], w3 = B[3 * HH], w4 = B[4 * HH], w5 = B[5 * HH];
#pragma unroll 4
    for (int i = 0; i < 32; i++) {
        float acc = w0 * xi[i][0] + w1 * xi[i][1] + w2 * xi[i][2] +
                    w3 * xi[i][3] + w4 * xi[i][4] + w5 * xi[i][5];
        int n = n0 + i;
        if (c < 128) g_ts[(size_t)n * 128 + c] = __float2half_rn(acc);
        else         g_tn[(size_t)n * 128 + (c - 128)] = __float2half_rn(acc);
    }
}

// ---------------- combine (body): agg+bias+relu -> feat cols of buffer[layer] ----
__global__ void __launch_bounds__(256)
combine_body_kernel(const float* __restrict__ bias, int layer) {
    uint64_t pel = pol_evict_last();
    uint64_t pef = pol_evict_first();
    int gw = (blockIdx.x * blockDim.x + threadIdx.x) >> 5;
    int lane = threadIdx.x & 31;
    if (gw >= NN) return;
    int n = gw;
    int s0 = g_off[n], s1 = g_off[n + 1];
    float4 acc = make_float4(0.f, 0.f, 0.f, 0.f);
    int e = s0;
    for (; e + 4 <= s1; e += 4) {
        int i0 = g_csr[e], i1 = g_csr[e + 1], i2 = g_csr[e + 2], i3 = g_csr[e + 3];
        float4 v0 = ldh_hint_f4(g_tn + (size_t)i0 * 128 + lane * 4, pel);
        float4 v1 = ldh_hint_f4(g_tn + (size_t)i1 * 128 + lane * 4, pel);
        float4 v2 = ldh_hint_f4(g_tn + (size_t)i2 * 128 + lane * 4, pel);
        float4 v3 = ldh_hint_f4(g_tn + (size_t)i3 * 128 + lane * 4, pel);
        acc.x += (v0.x + v1.x) + (v2.x + v3.x);
        acc.y += (v0.y + v1.y) + (v2.y + v3.y);
        acc.z += (v0.z + v1.z) + (v2.z + v3.z);
        acc.w += (v0.w + v1.w) + (v2.w + v3.w);
    }
    for (; e < s1; e++) {
        int s = g_csr[e];
        float4 v = ldh_hint_f4(g_tn + (size_t)s * 128 + lane * 4, pel);
        acc.x += v.x; acc.y += v.y; acc.z += v.z; acc.w += v.w;
    }
    float inv = 1.0f / (float)max(s1 - s0, 1);
    float4 ts = ldh_hint_f4(g_ts + (size_t)n * 128 + lane * 4, pef);
    float4 b4 = ((const float4*)bias)[lane];
    float o[4];
    o[0] = fmaxf(ts.x + acc.x * inv + b4.x, 0.f);
    o[1] = fmaxf(ts.y + acc.y * inv + b4.y, 0.f);
    o[2] = fmaxf(ts.z + acc.z * inv + b4.z, 0.f);
    o[3] = fmaxf(ts.w + acc.w * inv + b4.w, 0.f);
    size_t base = ((size_t)layer * NN + n) * 256 + lane * 4;
    stg_hint_u2(g_Af + base, pack_h2(o[0], o[1]), pack_h2(o[2], o[3]), pef);
}

// ---------------- combine (head): agg+bias+relu + fused head GEMM -> g_q --------
__global__ void __launch_bounds__(256)
combine_head_kernel(const float* __restrict__ bias,
                    const float* __restrict__ Wls,
                    const float* __restrict__ Wln) {
    __shared__ float Bs[128][6];
    int tid = threadIdx.x;
    for (int i = tid; i < 128 * 6; i += 256) {
        int k = i / 6, c = i % 6;
        Bs[k][c] = (c < 3) ? Wls[k * 3 + c] : Wln[k * 3 + (c - 3)];
    }
    __syncthreads();
    uint64_t pel = pol_evict_last();
    uint64_t pef = pol_evict_first();
    int gw = (blockIdx.x * blockDim.x + tid) >> 5;
    int lane = tid & 31;
    if (gw >= NN) return;
    int n = gw;
    int s0 = g_off[n], s1 = g_off[n + 1];
    float4 acc = make_float4(0.f, 0.f, 0.f, 0.f);
    int e = s0;
    for (; e + 4 <= s1; e += 4) {
        int i0 = g_csr[e], i1 = g_csr[e + 1], i2 = g_csr[e + 2], i3 = g_csr[e + 3];
        float4 v0 = ldh_hint_f4(g_tn + (size_t)i0 * 128 + lane * 4, pel);
        float4 v1 = ldh_hint_f4(g_tn + (size_t)i1 * 128 + lane * 4, pel);
        float4 v2 = ldh_hint_f4(g_tn + (size_t)i2 * 128 + lane * 4, pel);
        float4 v3 = ldh_hint_f4(g_tn + (size_t)i3 * 128 + lane * 4, pel);
        acc.x += (v0.x + v1.x) + (v2.x + v3.x);
        acc.y += (v0.y + v1.y) + (v2.y + v3.y);
        acc.z += (v0.z + v1.z) + (v2.z + v3.z);
        acc.w += (v0.w + v1.w) + (v2.w + v3.w);
    }
    for (; e < s1; e++) {
        int s = g_csr[e];
        float4 v = ldh_hint_f4(g_tn + (size_t)s * 128 + lane * 4, pel);
        acc.x += v.x; acc.y += v.y; acc.z += v.z; acc.w += v.w;
    }
    float inv = 1.0f / (float)max(s1 - s0, 1);
    float4 ts = ldh_hint_f4(g_ts + (size_t)n * 128 + lane * 4, pef);
    float4 b4 = ((const float4*)bias)[lane];
    float o0 = fmaxf(ts.x + acc.x * inv + b4.x, 0.f);
    float o1 = fmaxf(ts.y + acc.y * inv + b4.y, 0.f);
    float o2 = fmaxf(ts.z + acc.z * inv + b4.z, 0.f);
    float o3 = fmaxf(ts.w + acc.w * inv + b4.w, 0.f);
    float p[6];
#pragma unroll
    for (int j = 0; j < 6; j++)
        p[j] = o0 * Bs[lane * 4 + 0][j] + o1 * Bs[lane * 4 + 1][j] +
               o2 * Bs[lane * 4 + 2][j] + o3 * Bs[lane * 4 + 3][j];
#pragma unroll
    for (int off = 16; off > 0; off >>= 1) {
#pragma unroll
        for (int j = 0; j < 6; j++)
            p[j] += __shfl_xor_sync(0xffffffff, p[j], off);
    }
    if (lane == 0) {
#pragma unroll
        for (int j = 0; j < 6; j++)
            g_q[(size_t)n * 6 + j] = p[j];
    }
}

// ---------------- body GEMM: tcgen05 fp16 (A single, W hi/lo), K=208 -------------
// stage = A(16KB) + Wh(32KB) + Wl(32KB) = 80KB; 2 stages
#define ST_A 0
#define ST_WH 16384
#define ST_WL 49152
#define ST_BYTES 81920
#define SMEM_TILES 1024
#define GEMM_SMEM (SMEM_TILES + 2 * ST_BYTES)   // 164864

__global__ void __launch_bounds__(256, 1)
tc_gemm_kernel(int layer) {
#if TC_OK
    extern __shared__ char smem[];
    uint32_t sb = smem_to_u32(smem);
    int tid = threadIdx.x;
    int wid = tid >> 5;
    int row0 = blockIdx.x * 128;
    uint64_t pel = pol_evict_last();
    uint64_t pef = pol_evict_first();

    if (wid == 0) {
        TCGEN05_ALLOC(sb, 256);
        TCGEN05_RELINQ();
    }
    if (tid == 0) {
        MBARRIER_INIT(sb + 8, 1);
        MBARRIER_INIT(sb + 16, 1);
    }
    __syncthreads();
    uint32_t tmem;
    asm volatile("ld.shared.b32 %0, [%1];" : "=r"(tmem) : "r"(sb));

    const __half* Af = g_Af + (size_t)layer * NN * 256;
    const __half* Wh = g_Wh + (size_t)layer * 65536;
    const __half* Wl = g_Wl + (size_t)layer * 65536;

    auto load_stage = [&](int kc, int st, bool full) {
        char* base = smem + SMEM_TILES + st * ST_BYTES;
        int c0 = kc * 64;
        if (full) {
#pragma unroll
            for (int i = 0; i < 4; i++) {           // A: 1024 16B units
                int u = tid + i * 256;
                int m = u >> 3, j = u & 7;
                int n = row0 + m;
                uint4 va = make_uint4(0u, 0u, 0u, 0u);
                if (n < NN) va = ldg_hint_u4(Af + (size_t)n * 256 + c0 + j * 8, pef);
                uint32_t off = SMEM_SWIZZLE_128B((uint32_t)(m * 128 + j * 16));
                *(uint4*)(base + ST_A + off) = va;
            }
#pragma unroll
            for (int i = 0; i < 8; i++) {           // Wh + Wl: 2048 units each
                int u = tid + i * 256;
                int r = u >> 3, j = u & 7;
                uint4 vh = ldg_hint_u4(Wh + (size_t)r * 256 + c0 + j * 8, pel);
                uint4 vl = ldg_hint_u4(Wl + (size_t)r * 256 + c0 + j * 8, pel);
                uint32_t off = SMEM_SWIZZLE_128B((uint32_t)(r * 128 + j * 16));
                *(uint4*)(base + ST_WH + off) = vh;
                *(uint4*)(base + ST_WL + off) = vl;
            }
        } else {
            {
                int m = tid >> 1, j = tid & 1;
                int n = row0 + m;
                uint4 va = make_uint4(0u, 0u, 0u, 0u);
                if (n < NN) va = ldg_hint_u4(Af + (size_t)n * 256 + c0 + j * 8, pef);
                uint32_t off = SMEM_SWIZZLE_128B((uint32_t)(m * 128 + j * 16));
                *(uint4*)(base + ST_A + off) = va;
            }
#pragma unroll
            for (int i = 0; i < 2; i++) {
                int u = tid + i * 256;
                int r = u >> 1, j = u & 1;
                uint4 vh = ldg_hint_u4(Wh + (size_t)r * 256 + c0 + j * 8, pel);
                uint4 vl = ldg_hint_u4(Wl + (size_t)r * 256 + c0 + j * 8, pel);
                uint32_t off = SMEM_SWIZZLE_128B((uint32_t)(r * 128 + j * 16));
                *(uint4*)(base + ST_WH + off) = vh;
                *(uint4*)(base + ST_WL + off) = vl;
            }
        }
    };

    load_stage(0, 0, true);
    FENCE_ASYNC();
    __syncthreads();

    for (int c = 0; c < 4; c++) {
        int st = c & 1;
        int nk = (c < 3) ? 4 : 1;
        if (wid == 0 && elect_one_pred()) {
            uint32_t tb = sb + SMEM_TILES + st * ST_BYTES;
            uint64_t a  = make_desc(tb + ST_A);
            uint64_t wh = make_desc(tb + ST_WH);
            uint64_t wl = make_desc(tb + ST_WL);
            for (int k = 0; k < nk; k++) {
                bool en = !(c == 0 && k == 0);
                mma_f16_ss(tmem,       a + k * 2, wh + k * 2,        MMA_IDESC, en);
                mma_f16_ss(tmem,       a + k * 2, wl + k * 2,        MMA_IDESC, true);
                mma_f16_ss(tmem + 128, a + k * 2, wh + 1024 + k * 2, MMA_IDESC, en);
                mma_f16_ss(tmem + 128, a + k * 2, wl + 1024 + k * 2, MMA_IDESC, true);
            }
            TCGEN05_COMMIT(sb + 8 + 8 * st);
        }
        if (c < 3) {
            if (c >= 1) MBARRIER_WAIT_PARITY(sb + 8 + 8 * ((c + 1) & 1), 0);
            load_stage(c + 1, st ^ 1, (c + 1) < 3);
            FENCE_ASYNC();
        }
        __syncthreads();
    }

    MBARRIER_WAIT_PARITY(sb + 8, 1);
    MBARRIER_WAIT_PARITY(sb + 16, 1);
    TCGEN05_FENCE_AFTER();

    if (wid < 4) {
        int lane = tid & 31;
        int n = row0 + wid * 32 + lane;
#pragma unroll
        for (int cb = 0; cb < 256; cb += 32) {
            uint32_t r[32];
            TCGEN05_LD_X32(r, tmem + cb);
            TCGEN05_WAIT_LD();
            if (n < NN) {
                __half* dst = (cb < 128 ? g_ts : g_tn) + (size_t)n * 128 + (cb & 127);
                uint64_t pol = (cb < 128) ? pef : pel;
                uint32_t hp[16];
#pragma unroll
                for (int j = 0; j < 16; j++)
                    hp[j] = pack_h2(__uint_as_float(r[2 * j]),
                                    __uint_as_float(r[2 * j + 1]));
#pragma unroll
                for (int j = 0; j < 4; j++)
                    stg_hint_u4(dst + j * 8,
                                make_uint4(hp[4 * j], hp[4 * j + 1],
                                           hp[4 * j + 2], hp[4 * j + 3]), pol);
            }
        }
        TCGEN05_FENCE_BEFORE();
    }
    __syncthreads();
    if (wid == 0) TCGEN05_DEALLOC(tmem, 256);
#else
    // ------- SIMT f32x2 fallback -------
    extern __shared__ char smem[];
    float (*As)[16][132] = reinterpret_cast<float(*)[16][132]>(smem);
    float (*Bs)[16][128] = reinterpret_cast<float(*)[16][128]>(smem + 2 * 16 * 132 * 4);

    const int tid = threadIdx.x;
    const int tx = tid & 15;
    const int ty = tid >> 4;
    const int row0 = blockIdx.x * 128;
    const float* Wf = g_Wf + (size_t)layer * 65536;
    const __half* Af = g_Af + (size_t)layer * NN * 256;

    for (int half = 0; half < 2; half++) {
        const int col0 = half * 128;
        unsigned long long acc[8][4];
#pragma unroll
        for (int i = 0; i < 8; i++)
#pragma unroll
            for (int j = 0; j < 4; j++) acc[i][j] = 0ull;

        float ra[8], rb[8];
        auto loadA = [&](int kt, float* r) {
            int kbase = kt * 16;
#pragma unroll
            for (int j = 0; j < 8; j++) {
                int l = tid + j * 256;
                int m = l >> 4, kk = l & 15;
                int n = row0 + m;
                int k = kbase + kk;
                float v = 0.f;
                if (n < NN) v = __half2float(Af[(size_t)n * 256 + k]);
                r[j] = v;
            }
        };
        auto loadB = [&](int kt, float* r) {
            int kbase = kt * 16;
#pragma unroll
            for (int j = 0; j < 8; j++) {
                int l = tid + j * 256;
                int c = l & 127;
                int k = kbase + (l >> 7);
                r[j] = Wf[(size_t)k * 256 + col0 + c];
            }
        };
        auto storeA = [&](int st, const float* r) {
#pragma unroll
            for (int j = 0; j < 8; j++) {
                int l = tid + j * 256;
                As[st][l & 15][l >> 4] = r[j];
            }
        };
        auto storeB = [&](int st, const float* r) {
#pragma unroll
            for (int j = 0; j < 8; j++) {
                int l = tid + j * 256;
                Bs[st][l >> 7][l & 127] = r[j];
            }
        };

        loadA(0, ra); loadB(0, rb);
        storeA(0, ra); storeB(0, rb);
        __syncthreads();

        for (int kt = 0; kt < 13; kt++) {
            int cur = kt & 1;
            if (kt < 12) { loadA(kt + 1, ra); loadB(kt + 1, rb); }
#pragma unroll
            for (int kk = 0; kk < 16; kk++) {
                float4 a0 = *(const float4*)&As[cur][kk][ty * 8];
                float4 a1 = *(const float4*)&As[cur][kk][ty * 8 + 4];
                ulonglong2 b0 = *(const ulonglong2*)&Bs[cur][kk][tx * 4];
                ulonglong2 b1 = *(const ulonglong2*)&Bs[cur][kk][64 + tx * 4];
                unsigned long long ad[8];
                ad[0] = pack2(a0.x, a0.x); ad[1] = pack2(a0.y, a0.y);
                ad[2] = pack2(a0.z, a0.z); ad[3] = pack2(a0.w, a0.w);
                ad[4] = pack2(a1.x, a1.x); ad[5] = pack2(a1.y, a1.y);
                ad[6] = pack2(a1.z, a1.z); ad[7] = pack2(a1.w, a1.w);
#pragma unroll
                for (int i = 0; i < 8; i++) {
                    acc[i][0] = fma2(ad[i], b0.x, acc[i][0]);
                    acc[i][1] = fma2(ad[i], b0.y, acc[i][1]);
                    acc[i][2] = fma2(ad[i], b1.x, acc[i][2]);
                    acc[i][3] = fma2(ad[i], b1.y, acc[i][3]);
                }
            }
            if (kt < 12) { storeA(cur ^ 1, ra); storeB(cur ^ 1, rb); }
            __syncthreads();
        }

#pragma unroll
        for (int i = 0; i < 8; i++) {
            int n = row0 + ty * 8 + i;
            if (n < NN) {
                float vals[8];
                *(ulonglong2*)&vals[0] = *(ulonglong2*)&acc[i][0];
                *(ulonglong2*)&vals[4] = *(ulonglong2*)&acc[i][2];
                __half* base = (half == 0 ? g_ts : g_tn) + (size_t)n * 128;
#pragma unroll
                for (int j = 0; j < 4; j++) base[tx * 4 + j] = __float2half_rn(vals[j]);
#pragma unroll
                for (int j = 0; j < 4; j++) base[64 + tx * 4 + j] = __float2half_rn(vals[4 + j]);
            }
        }
        __syncthreads();
    }
#endif
}

// ---------------- final combine: out = q_s + agg(q_n)/deg + bl ----------------
__global__ void final_combine_kernel(const float* __restrict__ bl,
                                     float* __restrict__ out) {
    int n = blockIdx.x * blockDim.x + threadIdx.x;
    if (n >= NN) return;
    int s0 = g_off[n], s1 = g_off[n + 1];
    float a0 = 0.f, a1 = 0.f, a2 = 0.f;
    for (int e = s0; e < s1; e++) {
        int s = g_csr[e];
        a0 += g_q[(size_t)s * 6 + 3];
        a1 += g_q[(size_t)s * 6 + 4];
        a2 += g_q[(size_t)s * 6 + 5];
    }
    float inv = 1.0f / (float)max(s1 - s0, 1);
    out[n * 3 + 0] = g_q[(size_t)n * 6 + 0] + a0 * inv + bl[0];
    out[n * 3 + 1] = g_q[(size_t)n * 6 + 1] + a1 * inv + bl[1];
    out[n * 3 + 2] = g_q[(size_t)n * 6 + 2] + a2 * inv + bl[2];
}

// ---------------- launch ----------------
extern "C" void kernel_launch(void* const* d_in, const int* in_sizes, int n_in,
                              void* d_out, int out_size) {
    const float* vert = (const float*)d_in[0];
    const void*  edges = d_in[1];
    const float* vpot = (const float*)d_in[2];
    const float* z    = (const float*)d_in[3];
    const float* W0s  = (const float*)d_in[4];
    const float* W0n  = (const float*)d_in[5];
    const float* b0   = (const float*)d_in[6];
    const float* Wbs  = (const float*)d_in[7];
    const float* Wbn  = (const float*)d_in[8];
    const float* bb   = (const float*)d_in[9];
    const float* Wls  = (const float*)d_in[10];
    const float* Wln  = (const float*)d_in[11];
    const float* bl   = (const float*)d_in[12];
    float* out = (float*)d_out;

    static cudaStream_t sB = nullptr;
    static cudaEvent_t evFork = nullptr, evJoin = nullptr;
    static bool attr_set = false;
    if (!attr_set) {
        cudaFuncSetAttribute(tc_gemm_kernel, cudaFuncAttributeMaxDynamicSharedMemorySize, GEMM_SMEM);
        cudaStreamCreateWithFlags(&sB, cudaStreamNonBlocking);
        cudaEventCreateWithFlags(&evFork, cudaEventDisableTiming);
        cudaEventCreateWithFlags(&evJoin, cudaEventDisableTiming);
        attr_set = true;
    }

    // ---- fork: prep chain on sB, CSR chain on default stream ----
    cudaEventRecord(evFork, 0);
    cudaStreamWaitEvent(sB, evFork, 0);

    wconv_kernel<<<1024, 256, 0, sB>>>(Wbs, Wbn);
    prep_kernel<<<(int)((4LL * NN * 40 + 255) / 256), 256, 0, sB>>>(z, vert, vpot);
    l0_gemm_kernel<<<NN / 32, 256, 0, sB>>>(vert, vpot, W0s, W0n);
    cudaEventRecord(evJoin, sB);

    // default stream: CSR build
    zero_counts_kernel<<<(NN + 1023) / 1024, 1024>>>(edges);
    count_kernel<<<(EE + 255) / 256, 256>>>(edges);
    scan_block_kernel<<<SCAN_BLOCKS, 1024>>>();
    scan_tops_kernel<<<1, 128>>>();
    scan_add_kernel<<<SCAN_BLOCKS, 1024>>>();
    scatter_kernel<<<(EE + 255) / 256, 256>>>(edges);

    cudaStreamWaitEvent(0, evJoin, 0);

    // layer 0 combine -> A buffer 0
    combine_body_kernel<<<(NN * 32 + 255) / 256, 256>>>(b0, 0);

    // 4 body layers
    for (int i = 0; i < 4; i++) {
        tc_gemm_kernel<<<MTILES, 256, GEMM_SMEM>>>(i);
        if (i < 3)
            combine_body_kernel<<<(NN * 32 + 255) / 256, 256>>>(bb + i * HH, i + 1);
        else
            combine_head_kernel<<<(NN * 32 + 255) / 256, 256>>>(bb + 3 * HH, Wls, Wln);
    }

    // head
    final_combine_kernel<<<(NN + 255) / 256, 256>>>(bl, out);
}

// round 17
// speedup vs baseline: 1.6220x; 1.1727x over previous
#include <cuda_runtime.h>
#include <cuda_bf16.h>
#include <cuda_fp16.h>
#include <cstdint>

#define NN 100000
#define EE 600000
#define HH 128
#define ZZ 64
#define BIN 198
#define SCAN_BLOCKS ((NN + 1023) / 1024)   // 98
#define MTILES ((NN + 127) / 128)          // 782

// ---------------- device scratch (no allocations allowed) ----------------
__device__ int    g_i64;
__device__ int    g_counts[NN];
__device__ int    g_off[NN + 1];
__device__ int    g_cursor[NN];
__device__ int    g_csr[EE];
__device__ int    g_bsums[SCAN_BLOCKS];
__device__ int    g_bsum_ex[SCAN_BLOCKS];
__device__ __half g_ts[(size_t)NN * 128];              // GEMM out, s-half (fp16, streamed)
__device__ __half g_tn[(size_t)NN * 128];              // GEMM out, n-half (fp16; L2-hot)
__device__ float  g_q[(size_t)NN * 6];                 // head per-node outputs
__device__ __half g_Af[(size_t)4 * NN * 256];          // per-layer concat A (fp16)
__device__ __half g_Wh[4 * 256 * 256];                 // weights fp16 [layer][n][k]
__device__ float  g_Wf[4 * 256 * 256];                 // fp32 [l][k][n] (fallback path)

// ---------------- arch feature gate ----------------
#if defined(__CUDA_ARCH_FEAT_SM103_ALL) || defined(__CUDA_ARCH_FEAT_SM100_ALL) || \
    defined(__CUDA_ARCH_FEAT_SM101_ALL) || defined(__CUDA_ARCH_FEAT_SM110_ALL)
#define TC_OK 1
#else
#define TC_OK 0
#endif

// ---------------- L2 policy-based cache hints ----------------
__device__ __forceinline__ uint64_t pol_evict_last() {
    uint64_t p;
    asm("createpolicy.fractional.L2::evict_last.b64 %0, 1.0;" : "=l"(p));
    return p;
}
__device__ __forceinline__ uint64_t pol_evict_first() {
    uint64_t p;
    asm("createpolicy.fractional.L2::evict_first.b64 %0, 1.0;" : "=l"(p));
    return p;
}
__device__ __forceinline__ uint4 ldg_hint_u4(const void* p, uint64_t pol) {
    uint4 v;
    asm volatile("ld.global.nc.L2::cache_hint.v4.b32 {%0,%1,%2,%3}, [%4], %5;"
                 : "=r"(v.x), "=r"(v.y), "=r"(v.z), "=r"(v.w) : "l"(p), "l"(pol));
    return v;
}
__device__ __forceinline__ void stg_hint_u4(void* p, uint4 v, uint64_t pol) {
    asm volatile("st.global.L2::cache_hint.v4.b32 [%0], {%1,%2,%3,%4}, %5;"
                 :: "l"(p), "r"(v.x), "r"(v.y), "r"(v.z), "r"(v.w), "l"(pol) : "memory");
}
__device__ __forceinline__ float4 ldh_hint_f4(const __half* p, uint64_t pol) {
    uint32_t a, b;
    asm volatile("ld.global.nc.L2::cache_hint.v2.b32 {%0,%1}, [%2], %3;"
                 : "=r"(a), "=r"(b) : "l"(p), "l"(pol));
    __half2 h0 = *reinterpret_cast<__half2*>(&a);
    __half2 h1 = *reinterpret_cast<__half2*>(&b);
    float2 f0 = __half22float2(h0);
    float2 f1 = __half22float2(h1);
    return make_float4(f0.x, f0.y, f1.x, f1.y);
}
__device__ __forceinline__ uint32_t pack_h2(float lo, float hi) {
    __half2 h = __floats2half2_rn(lo, hi);
    return *reinterpret_cast<uint32_t*>(&h);
}
__device__ __forceinline__ void stg_hint_u2(void* p, uint32_t a, uint32_t b, uint64_t pol) {
    asm volatile("st.global.L2::cache_hint.v2.b32 [%0], {%1,%2}, %3;"
                 :: "l"(p), "r"(a), "r"(b), "l"(pol) : "memory");
}

// ---------------- PTX helpers ----------------
__device__ __forceinline__ uint32_t elect_one_pred() {
    uint32_t pred;
    asm volatile("{\n\t.reg .pred p;\n\telect.sync _|p, 0xFFFFFFFF;\n\tselp.b32 %0, 1, 0, p;\n\t}"
                 : "=r"(pred));
    return pred;
}
__device__ __forceinline__ uint32_t smem_to_u32(const void* p) {
    uint32_t a;
    asm("{ .reg .u64 t; cvta.to.shared.u64 t, %1; cvt.u32.u64 %0, t; }" : "=r"(a) : "l"(p));
    return a;
}
#define SMEM_SWIZZLE_128B(x) ((x) ^ (((x) >> 3) & 0x70))

#define TCGEN05_ALLOC(sa, n) \
    asm volatile("tcgen05.alloc.cta_group::1.sync.aligned.shared::cta.b32 [%0], %1;" \
                 :: "r"((uint32_t)(sa)), "r"((uint32_t)(n)) : "memory")
#define TCGEN05_DEALLOC(t, n) \
    asm volatile("tcgen05.dealloc.cta_group::1.sync.aligned.b32 %0, %1;" :: "r"(t), "r"(n))
#define TCGEN05_RELINQ() \
    asm volatile("tcgen05.relinquish_alloc_permit.cta_group::1.sync.aligned;")
#define TCGEN05_COMMIT(mb) \
    asm volatile("tcgen05.commit.cta_group::1.mbarrier::arrive::one.shared::cluster.b64 [%0];" \
                 :: "r"((uint32_t)(mb)) : "memory")
#define TCGEN05_FENCE_AFTER() asm volatile("tcgen05.fence::after_thread_sync;" ::: "memory")
#define TCGEN05_FENCE_BEFORE() asm volatile("tcgen05.fence::before_thread_sync;" ::: "memory")
#define TCGEN05_WAIT_LD() asm volatile("tcgen05.wait::ld.sync.aligned;" ::: "memory")
#define FENCE_ASYNC() asm volatile("fence.proxy.async.shared::cta;" ::: "memory")
#define MBARRIER_INIT(mb, c) \
    asm volatile("mbarrier.init.shared.b64 [%0], %1;" :: "r"((uint32_t)(mb)), "r"((uint32_t)(c)) : "memory")

#define MBARRIER_WAIT_PARITY(mb, ph) do { \
    uint32_t _m = (uint32_t)(mb), _p = (uint32_t)(ph), _d; \
    asm volatile("{\n\t.reg .pred p;\n\t" \
        "mbarrier.try_wait.parity.acquire.cta.shared::cta.b64 p, [%1], %2;\n\t" \
        "selp.b32 %0, 1, 0, p;\n\t}" : "=r"(_d) : "r"(_m), "r"(_p) : "memory"); \
    if (!_d) { \
        asm volatile("{\n\t.reg .pred P1;\n\t" \
            "WL_%=:\n\t" \
            "mbarrier.try_wait.parity.acquire.cta.shared::cta.b64 P1, [%0], %1, 0x989680;\n\t" \
            "@P1 bra.uni WD_%=;\n\tbra.uni WL_%=;\n\tWD_%=:\n\t}" \
            :: "r"(_m), "r"(_p) : "memory"); \
    } \
} while (0)

#define TCGEN05_LD_X32(r, ta) \
    asm volatile("tcgen05.ld.sync.aligned.32x32b.x32.b32 " \
        "{%0, %1, %2, %3, %4, %5, %6, %7, %8, %9, %10, %11, %12, %13, %14, %15, " \
        "%16, %17, %18, %19, %20, %21, %22, %23, %24, %25, %26, %27, %28, %29, %30, %31}, [%32];" \
        : "=r"((r)[0]), "=r"((r)[1]), "=r"((r)[2]), "=r"((r)[3]), "=r"((r)[4]), "=r"((r)[5]), \
          "=r"((r)[6]), "=r"((r)[7]), "=r"((r)[8]), "=r"((r)[9]), "=r"((r)[10]), "=r"((r)[11]), \
          "=r"((r)[12]), "=r"((r)[13]), "=r"((r)[14]), "=r"((r)[15]), "=r"((r)[16]), "=r"((r)[17]), \
          "=r"((r)[18]), "=r"((r)[19]), "=r"((r)[20]), "=r"((r)[21]), "=r"((r)[22]), "=r"((r)[23]), \
          "=r"((r)[24]), "=r"((r)[25]), "=r"((r)[26]), "=r"((r)[27]), "=r"((r)[28]), "=r"((r)[29]), \
          "=r"((r)[30]), "=r"((r)[31]) : "r"(ta))

#if TC_OK
__device__ __forceinline__ void mma_f16_ss(uint32_t d, uint64_t a, uint64_t b,
                                           uint32_t idesc, bool en) {
    uint32_t e = en ? 1u : 0u;
    asm volatile(
        "{\n\t.reg .pred p;\n\tsetp.ne.u32 p, %5, 0;\n\t"
        "tcgen05.mma.cta_group::1.kind::f16 [%0], %1, %2, %3, {%4, %4, %4, %4}, p;\n\t}"
        :: "r"(d), "l"(a), "l"(b), "r"(idesc), "r"(0u), "r"(e) : "memory");
}
#endif

__device__ __forceinline__ uint64_t make_desc(uint32_t addr) {
    const uint64_t base = (2ull << 61) | (1ull << 46) | (64ull << 32) | (1ull << 16);
    return base | ((uint64_t)(addr >> 4) & 0x3FFF);
}

// idesc: F32 accum, F16 a/b, N=128, M=128
#define MMA_IDESC ((1u << 4) | ((128u / 8) << 17) | ((128u / 16) << 24))

__device__ __forceinline__ int2 edge_pair(const void* edges, int e) {
    if (g_i64) {
        longlong2 v = ((const longlong2*)edges)[e];
        return make_int2((int)v.x, (int)v.y);
    }
    return ((const int2*)edges)[e];
}
__device__ __forceinline__ unsigned long long pack2(float x, float y) {
    unsigned long long d;
    asm("mov.b64 %0, {%1, %2};" : "=l"(d) : "f"(x), "f"(y));
    return d;
}
__device__ __forceinline__ unsigned long long fma2(unsigned long long a,
                                                   unsigned long long b,
                                                   unsigned long long c) {
    unsigned long long d;
    asm("fma.rn.f32x2 %0, %1, %2, %3;" : "=l"(d) : "l"(a), "l"(b), "l"(c));
    return d;
}

// ---------------- CSR construction ----------------
__global__ void zero_counts_kernel(const void* edges) {
    int i = blockIdx.x * blockDim.x + threadIdx.x;
    if (i < NN) g_counts[i] = 0;
    if (blockIdx.x == 0 && threadIdx.x < 32) {
        const long long* p = (const long long*)edges;
        long long v = p[threadIdx.x];
        bool ok = (v >= 0 && v < NN);
        unsigned m = __ballot_sync(0xffffffff, ok);
        if (threadIdx.x == 0) g_i64 = (m == 0xffffffffu) ? 1 : 0;
    }
}
__global__ void count_kernel(const void* edges) {
    int e = blockIdx.x * blockDim.x + threadIdx.x;
    if (e < EE) atomicAdd(&g_counts[edge_pair(edges, e).y], 1);
}
__global__ void scan_block_kernel() {
    __shared__ int s[1024];
    int t = threadIdx.x;
    int i = blockIdx.x * 1024 + t;
    int v = (i < NN) ? g_counts[i] : 0;
    s[t] = v;
    __syncthreads();
#pragma unroll
    for (int d = 1; d < 1024; d <<= 1) {
        int x = (t >= d) ? s[t - d] : 0;
        __syncthreads();
        s[t] += x;
        __syncthreads();
    }
    if (i < NN) g_off[i] = s[t] - v;
    if (t == 1023) g_bsums[blockIdx.x] = s[1023];
}
__global__ void scan_tops_kernel() {
    __shared__ int s[128];
    int t = threadIdx.x;
    int v = (t < SCAN_BLOCKS) ? g_bsums[t] : 0;
    s[t] = v;
    __syncthreads();
#pragma unroll
    for (int d = 1; d < 128; d <<= 1) {
        int x = (t >= d) ? s[t - d] : 0;
        __syncthreads();
        s[t] += x;
        __syncthreads();
    }
    if (t < SCAN_BLOCKS) g_bsum_ex[t] = s[t] - v;
}
__global__ void scan_add_kernel() {
    int i = blockIdx.x * 1024 + threadIdx.x;
    if (i < NN) {
        int o = g_off[i] + g_bsum_ex[blockIdx.x];
        g_off[i] = o;
        g_cursor[i] = o;
    }
    if (i == 0) g_off[NN] = EE;
}
__global__ void scatter_kernel(const void* edges) {
    int e = blockIdx.x * blockDim.x + threadIdx.x;
    if (e < EE) {
        int2 p = edge_pair(edges, e);
        g_csr[atomicAdd(&g_cursor[p.y], 1)] = p.x;
    }
}

// ---------------- weight transpose (fp16) ----------------
__global__ void wconv_kernel(const float* __restrict__ Wbs, const float* __restrict__ Wbn) {
    int idx = blockIdx.x * 256 + threadIdx.x;   // 4*256*256
    int l = idx >> 16, n = (idx >> 8) & 255, k = idx & 255;
    float v = 0.f;
    if (k < BIN)
        v = (n < 128) ? Wbs[(size_t)l * BIN * HH + k * 128 + n]
                      : Wbn[(size_t)l * BIN * HH + k * 128 + (n - 128)];
    g_Wh[idx] = __float2half_rn(v);
    g_Wf[(((size_t)l * 256) + k) * 256 + n] = v;
}

// ---------------- prep: fill z/in6/pad cols [128,208) of all 4 A buffers ---------
__global__ void __launch_bounds__(256)
prep_kernel(const float* __restrict__ z,
            const float* __restrict__ vert,
            const float* __restrict__ vpot) {
    long long idx = (long long)blockIdx.x * 256 + threadIdx.x;   // 4*NN*40
    if (idx >= 4LL * NN * 40) return;
    int t = (int)(idx % 40);
    long long r = idx / 40;
    int n = (int)(r % NN);
    int l = (int)(r / NN);
    int c = 128 + t * 2;
    float v0, v1;
    if (c < 192) {
        float2 zv = *(const float2*)(z + ((size_t)l * NN + n) * 64 + (c - 128));
        v0 = zv.x; v1 = zv.y;
    } else if (c < 198) {
        int j0 = c - 192, j1 = c - 191;
        v0 = (j0 < 3) ? vert[n * 3 + j0] : vpot[n * 3 + j0 - 3];
        v1 = (j1 < 3) ? vert[n * 3 + j1] : vpot[n * 3 + j1 - 3];
    } else {
        v0 = 0.f; v1 = 0.f;
    }
    size_t base = ((size_t)l * NN + n) * 256 + c;
    *(uint32_t*)(g_Af + base) = pack_h2(v0, v1);
}

// ---------------- layer 0 GEMM: 32 nodes per block ----------------
__global__ void __launch_bounds__(256)
l0_gemm_kernel(const float* __restrict__ vert,
               const float* __restrict__ vpot,
               const float* __restrict__ W0s,
               const float* __restrict__ W0n) {
    __shared__ float xi[32][6];
    int t = threadIdx.x;
    int n0 = blockIdx.x * 32;
    if (t < 192) {
        int i = t / 6, k = t % 6;
        int n = n0 + i;
        xi[i][k] = (k < 3) ? vert[n * 3 + k] : vpot[n * 3 + (k - 3)];
    }
    __syncthreads();
    int c = t;
    const float* B = (c < 128) ? (W0s + c) : (W0n + (c - 128));
    float w0 = B[0], w1 = B[HH], w2 = B[2 * HH], w3 = B[3 * HH], w4 = B[4 * HH], w5 = B[5 * HH];
#pragma unroll 4
    for (int i = 0; i < 32; i++) {
        float acc = w0 * xi[i][0] + w1 * xi[i][1] + w2 * xi[i][2] +
                    w3 * xi[i][3] + w4 * xi[i][4] + w5 * xi[i][5];
        int n = n0 + i;
        if (c < 128) g_ts[(size_t)n * 128 + c] = __float2half_rn(acc);
        else         g_tn[(size_t)n * 128 + (c - 128)] = __float2half_rn(acc);
    }
}

// ---------------- combine (body): agg+bias+relu -> feat cols of buffer[layer] ----
__global__ void __launch_bounds__(256)
combine_body_kernel(const float* __restrict__ bias, int layer) {
    uint64_t pel = pol_evict_last();
    uint64_t pef = pol_evict_first();
    int gw = (blockIdx.x * blockDim.x + threadIdx.x) >> 5;
    int lane = threadIdx.x & 31;
    if (gw >= NN) return;
    int n = gw;
    int s0 = g_off[n], s1 = g_off[n + 1];
    float4 acc = make_float4(0.f, 0.f, 0.f, 0.f);
    int e = s0;
    for (; e + 4 <= s1; e += 4) {
        int i0 = g_csr[e], i1 = g_csr[e + 1], i2 = g_csr[e + 2], i3 = g_csr[e + 3];
        float4 v0 = ldh_hint_f4(g_tn + (size_t)i0 * 128 + lane * 4, pel);
        float4 v1 = ldh_hint_f4(g_tn + (size_t)i1 * 128 + lane * 4, pel);
        float4 v2 = ldh_hint_f4(g_tn + (size_t)i2 * 128 + lane * 4, pel);
        float4 v3 = ldh_hint_f4(g_tn + (size_t)i3 * 128 + lane * 4, pel);
        acc.x += (v0.x + v1.x) + (v2.x + v3.x);
        acc.y += (v0.y + v1.y) + (v2.y + v3.y);
        acc.z += (v0.z + v1.z) + (v2.z + v3.z);
        acc.w += (v0.w + v1.w) + (v2.w + v3.w);
    }
    for (; e < s1; e++) {
        int s = g_csr[e];
        float4 v = ldh_hint_f4(g_tn + (size_t)s * 128 + lane * 4, pel);
        acc.x += v.x; acc.y += v.y; acc.z += v.z; acc.w += v.w;
    }
    float inv = 1.0f / (float)max(s1 - s0, 1);
    float4 ts = ldh_hint_f4(g_ts + (size_t)n * 128 + lane * 4, pef);
    float4 b4 = ((const float4*)bias)[lane];
    float o[4];
    o[0] = fmaxf(ts.x + acc.x * inv + b4.x, 0.f);
    o[1] = fmaxf(ts.y + acc.y * inv + b4.y, 0.f);
    o[2] = fmaxf(ts.z + acc.z * inv + b4.z, 0.f);
    o[3] = fmaxf(ts.w + acc.w * inv + b4.w, 0.f);
    size_t base = ((size_t)layer * NN + n) * 256 + lane * 4;
    stg_hint_u2(g_Af + base, pack_h2(o[0], o[1]), pack_h2(o[2], o[3]), pef);
}

// ---------------- combine (head): agg+bias+relu + fused head GEMM -> g_q --------
__global__ void __launch_bounds__(256)
combine_head_kernel(const float* __restrict__ bias,
                    const float* __restrict__ Wls,
                    const float* __restrict__ Wln) {
    __shared__ float Bs[128][6];
    int tid = threadIdx.x;
    for (int i = tid; i < 128 * 6; i += 256) {
        int k = i / 6, c = i % 6;
        Bs[k][c] = (c < 3) ? Wls[k * 3 + c] : Wln[k * 3 + (c - 3)];
    }
    __syncthreads();
    uint64_t pel = pol_evict_last();
    uint64_t pef = pol_evict_first();
    int gw = (blockIdx.x * blockDim.x + tid) >> 5;
    int lane = tid & 31;
    if (gw >= NN) return;
    int n = gw;
    int s0 = g_off[n], s1 = g_off[n + 1];
    float4 acc = make_float4(0.f, 0.f, 0.f, 0.f);
    int e = s0;
    for (; e + 4 <= s1; e += 4) {
        int i0 = g_csr[e], i1 = g_csr[e + 1], i2 = g_csr[e + 2], i3 = g_csr[e + 3];
        float4 v0 = ldh_hint_f4(g_tn + (size_t)i0 * 128 + lane * 4, pel);
        float4 v1 = ldh_hint_f4(g_tn + (size_t)i1 * 128 + lane * 4, pel);
        float4 v2 = ldh_hint_f4(g_tn + (size_t)i2 * 128 + lane * 4, pel);
        float4 v3 = ldh_hint_f4(g_tn + (size_t)i3 * 128 + lane * 4, pel);
        acc.x += (v0.x + v1.x) + (v2.x + v3.x);
        acc.y += (v0.y + v1.y) + (v2.y + v3.y);
        acc.z += (v0.z + v1.z) + (v2.z + v3.z);
        acc.w += (v0.w + v1.w) + (v2.w + v3.w);
    }
    for (; e < s1; e++) {
        int s = g_csr[e];
        float4 v = ldh_hint_f4(g_tn + (size_t)s * 128 + lane * 4, pel);
        acc.x += v.x; acc.y += v.y; acc.z += v.z; acc.w += v.w;
    }
    float inv = 1.0f / (float)max(s1 - s0, 1);
    float4 ts = ldh_hint_f4(g_ts + (size_t)n * 128 + lane * 4, pef);
    float4 b4 = ((const float4*)bias)[lane];
    float o0 = fmaxf(ts.x + acc.x * inv + b4.x, 0.f);
    float o1 = fmaxf(ts.y + acc.y * inv + b4.y, 0.f);
    float o2 = fmaxf(ts.z + acc.z * inv + b4.z, 0.f);
    float o3 = fmaxf(ts.w + acc.w * inv + b4.w, 0.f);
    float p[6];
#pragma unroll
    for (int j = 0; j < 6; j++)
        p[j] = o0 * Bs[lane * 4 + 0][j] + o1 * Bs[lane * 4 + 1][j] +
               o2 * Bs[lane * 4 + 2][j] + o3 * Bs[lane * 4 + 3][j];
#pragma unroll
    for (int off = 16; off > 0; off >>= 1) {
#pragma unroll
        for (int j = 0; j < 6; j++)
            p[j] += __shfl_xor_sync(0xffffffff, p[j], off);
    }
    if (lane == 0) {
#pragma unroll
        for (int j = 0; j < 6; j++)
            g_q[(size_t)n * 6 + j] = p[j];
    }
}

// ---------------- body GEMM: tcgen05 fp16 (A single, W single), K=208 ------------
// stage = A(16KB) + Wh(32KB) = 48KB; 2 stages -> 97.3KB smem, 2 CTAs/SM
#define ST_A 0
#define ST_WH 16384
#define ST_BYTES 49152
#define SMEM_TILES 1024
#define GEMM_SMEM (SMEM_TILES + 2 * ST_BYTES)   // 99328

__global__ void __launch_bounds__(256)
tc_gemm_kernel(int layer) {
#if TC_OK
    extern __shared__ char smem[];
    uint32_t sb = smem_to_u32(smem);
    int tid = threadIdx.x;
    int wid = tid >> 5;
    int row0 = blockIdx.x * 128;
    uint64_t pel = pol_evict_last();
    uint64_t pef = pol_evict_first();

    if (wid == 0) {
        TCGEN05_ALLOC(sb, 256);
        TCGEN05_RELINQ();
    }
    if (tid == 0) {
        MBARRIER_INIT(sb + 8, 1);
        MBARRIER_INIT(sb + 16, 1);
    }
    __syncthreads();
    uint32_t tmem;
    asm volatile("ld.shared.b32 %0, [%1];" : "=r"(tmem) : "r"(sb));

    const __half* Af = g_Af + (size_t)layer * NN * 256;
    const __half* Wh = g_Wh + (size_t)layer * 65536;

    auto load_stage = [&](int kc, int st, bool full) {
        char* base = smem + SMEM_TILES + st * ST_BYTES;
        int c0 = kc * 64;
        if (full) {
#pragma unroll
            for (int i = 0; i < 4; i++) {           // A: 1024 16B units
                int u = tid + i * 256;
                int m = u >> 3, j = u & 7;
                int n = row0 + m;
                uint4 va = make_uint4(0u, 0u, 0u, 0u);
                if (n < NN) va = ldg_hint_u4(Af + (size_t)n * 256 + c0 + j * 8, pef);
                uint32_t off = SMEM_SWIZZLE_128B((uint32_t)(m * 128 + j * 16));
                *(uint4*)(base + ST_A + off) = va;
            }
#pragma unroll
            for (int i = 0; i < 8; i++) {           // Wh: 2048 units
                int u = tid + i * 256;
                int r = u >> 3, j = u & 7;
                uint4 vh = ldg_hint_u4(Wh + (size_t)r * 256 + c0 + j * 8, pel);
                uint32_t off = SMEM_SWIZZLE_128B((uint32_t)(r * 128 + j * 16));
                *(uint4*)(base + ST_WH + off) = vh;
            }
        } else {
            {
                int m = tid >> 1, j = tid & 1;
                int n = row0 + m;
                uint4 va = make_uint4(0u, 0u, 0u, 0u);
                if (n < NN) va = ldg_hint_u4(Af + (size_t)n * 256 + c0 + j * 8, pef);
                uint32_t off = SMEM_SWIZZLE_128B((uint32_t)(m * 128 + j * 16));
                *(uint4*)(base + ST_A + off) = va;
            }
#pragma unroll
            for (int i = 0; i < 2; i++) {
                int u = tid + i * 256;
                int r = u >> 1, j = u & 1;
                uint4 vh = ldg_hint_u4(Wh + (size_t)r * 256 + c0 + j * 8, pel);
                uint32_t off = SMEM_SWIZZLE_128B((uint32_t)(r * 128 + j * 16));
                *(uint4*)(base + ST_WH + off) = vh;
            }
        }
    };

    load_stage(0, 0, true);
    FENCE_ASYNC();
    __syncthreads();

    for (int c = 0; c < 4; c++) {
        int st = c & 1;
        int nk = (c < 3) ? 4 : 1;
        if (wid == 0 && elect_one_pred()) {
            uint32_t tb = sb + SMEM_TILES + st * ST_BYTES;
            uint64_t a  = make_desc(tb + ST_A);
            uint64_t wh = make_desc(tb + ST_WH);
            for (int k = 0; k < nk; k++) {
                bool en = !(c == 0 && k == 0);
                mma_f16_ss(tmem,       a + k * 2, wh + k * 2,        MMA_IDESC, en);
                mma_f16_ss(tmem + 128, a + k * 2, wh + 1024 + k * 2, MMA_IDESC, en);
            }
            TCGEN05_COMMIT(sb + 8 + 8 * st);
        }
        if (c < 3) {
            if (c >= 1) MBARRIER_WAIT_PARITY(sb + 8 + 8 * ((c + 1) & 1), 0);
            load_stage(c + 1, st ^ 1, (c + 1) < 3);
            FENCE_ASYNC();
        }
        __syncthreads();
    }

    MBARRIER_WAIT_PARITY(sb + 8, 1);
    MBARRIER_WAIT_PARITY(sb + 16, 1);
    TCGEN05_FENCE_AFTER();

    if (wid < 4) {
        int lane = tid & 31;
        int n = row0 + wid * 32 + lane;
#pragma unroll
        for (int cb = 0; cb < 256; cb += 32) {
            uint32_t r[32];
            TCGEN05_LD_X32(r, tmem + cb);
            TCGEN05_WAIT_LD();
            if (n < NN) {
                __half* dst = (cb < 128 ? g_ts : g_tn) + (size_t)n * 128 + (cb & 127);
                uint64_t pol = (cb < 128) ? pef : pel;
                uint32_t hp[16];
#pragma unroll
                for (int j = 0; j < 16; j++)
                    hp[j] = pack_h2(__uint_as_float(r[2 * j]),
                                    __uint_as_float(r[2 * j + 1]));
#pragma unroll
                for (int j = 0; j < 4; j++)
                    stg_hint_u4(dst + j * 8,
                                make_uint4(hp[4 * j], hp[4 * j + 1],
                                           hp[4 * j + 2], hp[4 * j + 3]), pol);
            }
        }
        TCGEN05_FENCE_BEFORE();
    }
    __syncthreads();
    if (wid == 0) TCGEN05_DEALLOC(tmem, 256);
#else
    // ------- SIMT f32x2 fallback -------
    extern __shared__ char smem[];
    float (*As)[16][132] = reinterpret_cast<float(*)[16][132]>(smem);
    float (*Bs)[16][128] = reinterpret_cast<float(*)[16][128]>(smem + 2 * 16 * 132 * 4);

    const int tid = threadIdx.x;
    const int tx = tid & 15;
    const int ty = tid >> 4;
    const int row0 = blockIdx.x * 128;
    const float* Wf = g_Wf + (size_t)layer * 65536;
    const __half* Af = g_Af + (size_t)layer * NN * 256;

    for (int half = 0; half < 2; half++) {
        const int col0 = half * 128;
        unsigned long long acc[8][4];
#pragma unroll
        for (int i = 0; i < 8; i++)
#pragma unroll
            for (int j = 0; j < 4; j++) acc[i][j] = 0ull;

        float ra[8], rb[8];
        auto loadA = [&](int kt, float* r) {
            int kbase = kt * 16;
#pragma unroll
            for (int j = 0; j < 8; j++) {
                int l = tid + j * 256;
                int m = l >> 4, kk = l & 15;
                int n = row0 + m;
                int k = kbase + kk;
                float v = 0.f;
                if (n < NN) v = __half2float(Af[(size_t)n * 256 + k]);
                r[j] = v;
            }
        };
        auto loadB = [&](int kt, float* r) {
            int kbase = kt * 16;
#pragma unroll
            for (int j = 0; j < 8; j++) {
                int l = tid + j * 256;
                int c = l & 127;
                int k = kbase + (l >> 7);
                r[j] = Wf[(size_t)k * 256 + col0 + c];
            }
        };
        auto storeA = [&](int st, const float* r) {
#pragma unroll
            for (int j = 0; j < 8; j++) {
                int l = tid + j * 256;
                As[st][l & 15][l >> 4] = r[j];
            }
        };
        auto storeB = [&](int st, const float* r) {
#pragma unroll
            for (int j = 0; j < 8; j++) {
                int l = tid + j * 256;
                Bs[st][l >> 7][l & 127] = r[j];
            }
        };

        loadA(0, ra); loadB(0, rb);
        storeA(0, ra); storeB(0, rb);
        __syncthreads();

        for (int kt = 0; kt < 13; kt++) {
            int cur = kt & 1;
            if (kt < 12) { loadA(kt + 1, ra); loadB(kt + 1, rb); }
#pragma unroll
            for (int kk = 0; kk < 16; kk++) {
                float4 a0 = *(const float4*)&As[cur][kk][ty * 8];
                float4 a1 = *(const float4*)&As[cur][kk][ty * 8 + 4];
                ulonglong2 b0 = *(const ulonglong2*)&Bs[cur][kk][tx * 4];
                ulonglong2 b1 = *(const ulonglong2*)&Bs[cur][kk][64 + tx * 4];
                unsigned long long ad[8];
                ad[0] = pack2(a0.x, a0.x); ad[1] = pack2(a0.y, a0.y);
                ad[2] = pack2(a0.z, a0.z); ad[3] = pack2(a0.w, a0.w);
                ad[4] = pack2(a1.x, a1.x); ad[5] = pack2(a1.y, a1.y);
                ad[6] = pack2(a1.z, a1.z); ad[7] = pack2(a1.w, a1.w);
#pragma unroll
                for (int i = 0; i < 8; i++) {
                    acc[i][0] = fma2(ad[i], b0.x, acc[i][0]);
                    acc[i][1] = fma2(ad[i], b0.y, acc[i][1]);
                    acc[i][2] = fma2(ad[i], b1.x, acc[i][2]);
                    acc[i][3] = fma2(ad[i], b1.y, acc[i][3]);
                }
            }
            if (kt < 12) { storeA(cur ^ 1, ra); storeB(cur ^ 1, rb); }
            __syncthreads();
        }

#pragma unroll
        for (int i = 0; i < 8; i++) {
            int n = row0 + ty * 8 + i;
            if (n < NN) {
                float vals[8];
                *(ulonglong2*)&vals[0] = *(ulonglong2*)&acc[i][0];
                *(ulonglong2*)&vals[4] = *(ulonglong2*)&acc[i][2];
                __half* base = (half == 0 ? g_ts : g_tn) + (size_t)n * 128;
#pragma unroll
                for (int j = 0; j < 4; j++) base[tx * 4 + j] = __float2half_rn(vals[j]);
#pragma unroll
                for (int j = 0; j < 4; j++) base[64 + tx * 4 + j] = __float2half_rn(vals[4 + j]);
            }
        }
        __syncthreads();
    }
#endif
}

// ---------------- final combine: out = q_s + agg(q_n)/deg + bl ----------------
__global__ void final_combine_kernel(const float* __restrict__ bl,
                                     float* __restrict__ out) {
    int n = blockIdx.x * blockDim.x + threadIdx.x;
    if (n >= NN) return;
    int s0 = g_off[n], s1 = g_off[n + 1];
    float a0 = 0.f, a1 = 0.f, a2 = 0.f;
    for (int e = s0; e < s1; e++) {
        int s = g_csr[e];
        a0 += g_q[(size_t)s * 6 + 3];
        a1 += g_q[(size_t)s * 6 + 4];
        a2 += g_q[(size_t)s * 6 + 5];
    }
    float inv = 1.0f / (float)max(s1 - s0, 1);
    out[n * 3 + 0] = g_q[(size_t)n * 6 + 0] + a0 * inv + bl[0];
    out[n * 3 + 1] = g_q[(size_t)n * 6 + 1] + a1 * inv + bl[1];
    out[n * 3 + 2] = g_q[(size_t)n * 6 + 2] + a2 * inv + bl[2];
}

// ---------------- launch ----------------
extern "C" void kernel_launch(void* const* d_in, const int* in_sizes, int n_in,
                              void* d_out, int out_size) {
    const float* vert = (const float*)d_in[0];
    const void*  edges = d_in[1];
    const float* vpot = (const float*)d_in[2];
    const float* z    = (const float*)d_in[3];
    const float* W0s  = (const float*)d_in[4];
    const float* W0n  = (const float*)d_in[5];
    const float* b0   = (const float*)d_in[6];
    const float* Wbs  = (const float*)d_in[7];
    const float* Wbn  = (const float*)d_in[8];
    const float* bb   = (const float*)d_in[9];
    const float* Wls  = (const float*)d_in[10];
    const float* Wln  = (const float*)d_in[11];
    const float* bl   = (const float*)d_in[12];
    float* out = (float*)d_out;

    static cudaStream_t sB = nullptr;
    static cudaEvent_t evFork = nullptr, evJoin = nullptr;
    static bool attr_set = false;
    if (!attr_set) {
        cudaFuncSetAttribute(tc_gemm_kernel, cudaFuncAttributeMaxDynamicSharedMemorySize, GEMM_SMEM);
        cudaStreamCreateWithFlags(&sB, cudaStreamNonBlocking);
        cudaEventCreateWithFlags(&evFork, cudaEventDisableTiming);
        cudaEventCreateWithFlags(&evJoin, cudaEventDisableTiming);
        attr_set = true;
    }

    // ---- fork: prep chain on sB, CSR chain on default stream ----
    cudaEventRecord(evFork, 0);
    cudaStreamWaitEvent(sB, evFork, 0);

    wconv_kernel<<<1024, 256, 0, sB>>>(Wbs, Wbn);
    prep_kernel<<<(int)((4LL * NN * 40 + 255) / 256), 256, 0, sB>>>(z, vert, vpot);
    l0_gemm_kernel<<<NN / 32, 256, 0, sB>>>(vert, vpot, W0s, W0n);
    cudaEventRecord(evJoin, sB);

    // default stream: CSR build
    zero_counts_kernel<<<(NN + 1023) / 1024, 1024>>>(edges);
    count_kernel<<<(EE + 255) / 256, 256>>>(edges);
    scan_block_kernel<<<SCAN_BLOCKS, 1024>>>();
    scan_tops_kernel<<<1, 128>>>();
    scan_add_kernel<<<SCAN_BLOCKS, 1024>>>();
    scatter_kernel<<<(EE + 255) / 256, 256>>>(edges);

    cudaStreamWaitEvent(0, evJoin, 0);

    // layer 0 combine -> A buffer 0
    combine_body_kernel<<<(NN * 32 + 255) / 256, 256>>>(b0, 0);

    // 4 body layers
    for (int i = 0; i < 4; i++) {
        tc_gemm_kernel<<<MTILES, 256, GEMM_SMEM>>>(i);
        if (i < 3)
            combine_body_kernel<<<(NN * 32 + 255) / 256, 256>>>(bb + i * HH, i + 1);
        else
            combine_head_kernel<<<(NN * 32 + 255) / 256, 256>>>(bb + 3 * HH, Wls, Wln);
    }

    // head
    final_combine_kernel<<<(NN + 255) / 256, 256>>>(bl, out);
}